// round 1
// baseline (speedup 1.0000x reference)
#include <cuda_runtime.h>
#include <math.h>

#define T_TOK 4096
#define D_EMB 1024
#define S_SEQ 2048
#define NH 16
#define HD 64
#define MLP_DIM 4096

// -------- scratch (device globals; no allocation allowed) --------
__device__ float g_xn[T_TOK * D_EMB];
__device__ float g_q[32 * S_SEQ * HD];
__device__ float g_k[32 * S_SEQ * HD];
__device__ float g_v[32 * S_SEQ * HD];
__device__ float g_o[T_TOK * D_EMB];
__device__ float g_x1[T_TOK * D_EMB];
__device__ float g_h[T_TOK * MLP_DIM];
__device__ float g_W2[D_EMB * D_EMB];
__device__ float g_b2[D_EMB];

// ---------------- LayerNorm: one block per row of 1024 ----------------
__global__ void __launch_bounds__(256) ln_kernel(const float* __restrict__ in,
                                                 const float* __restrict__ g,
                                                 const float* __restrict__ b,
                                                 float* __restrict__ out) {
    __shared__ float s_sum[256], s_sq[256];
    int row = blockIdx.x, tid = threadIdx.x;
    float4 v = ((const float4*)(in + (size_t)row * D_EMB))[tid];
    s_sum[tid] = v.x + v.y + v.z + v.w;
    s_sq[tid] = v.x * v.x + v.y * v.y + v.z * v.z + v.w * v.w;
    __syncthreads();
    for (int s = 128; s > 0; s >>= 1) {
        if (tid < s) { s_sum[tid] += s_sum[tid + s]; s_sq[tid] += s_sq[tid + s]; }
        __syncthreads();
    }
    float mean = s_sum[0] * (1.0f / D_EMB);
    float var = s_sq[0] * (1.0f / D_EMB) - mean * mean;
    float inv = rsqrtf(var + 1e-5f);
    float4 gg = ((const float4*)g)[tid];
    float4 bb = ((const float4*)b)[tid];
    float4 r;
    r.x = (v.x - mean) * inv * gg.x + bb.x;
    r.y = (v.y - mean) * inv * gg.y + bb.y;
    r.z = (v.z - mean) * inv * gg.z + bb.z;
    r.w = (v.w - mean) * inv * gg.w + bb.w;
    ((float4*)(out + (size_t)row * D_EMB))[tid] = r;
}

// ---------------- Fuse W2 = blockdiag(w_hproj) @ w_out ----------------
__global__ void __launch_bounds__(256) fuse_w2_kernel(const float* __restrict__ whp,
                                                      const float* __restrict__ wout,
                                                      float* __restrict__ W2) {
    __shared__ float hp[64 * 64];
    __shared__ float wo[64 * 64];
    int h = blockIdx.x, nt = blockIdx.y, tid = threadIdx.x;
#pragma unroll
    for (int j = 0; j < 4; j++) {
        int f = tid + 256 * j;
        ((float4*)hp)[f] = ((const float4*)(whp + (size_t)h * 4096))[f];
        int r = f >> 4, c4 = f & 15;
        *(float4*)&wo[r * 64 + c4 * 4] =
            *(const float4*)&wout[(size_t)(h * 64 + r) * D_EMB + nt * 64 + c4 * 4];
    }
    __syncthreads();
    int ty = tid >> 4, tx = tid & 15;
#pragma unroll
    for (int i = 0; i < 4; i++) {
        int d = ty * 4 + i;
#pragma unroll
        for (int j = 0; j < 4; j++) {
            int e = tx * 4 + j;
            float acc = 0.f;
#pragma unroll 8
            for (int k = 0; k < 64; k++) acc += hp[d * 64 + k] * wo[k * 64 + e];
            W2[(size_t)(h * 64 + d) * D_EMB + nt * 64 + e] = acc;
        }
    }
}

// bias2[e] = b_out[e] + sum_i b_hproj_flat[i] * w_out[i][e]
__global__ void __launch_bounds__(256) bias2_kernel(const float* __restrict__ bhp,
                                                    const float* __restrict__ bout,
                                                    const float* __restrict__ wout,
                                                    float* __restrict__ b2) {
    int e = blockIdx.x * 256 + threadIdx.x;
    float acc = bout[e];
    for (int i = 0; i < D_EMB; i++) acc += bhp[i] * wout[(size_t)i * D_EMB + e];
    b2[e] = acc;
}

// ---------------- Generic 128x128x16 SGEMM with epilogues ----------------
__device__ __forceinline__ float geluf(float x) {
    return 0.5f * x * (1.0f + erff(x * 0.70710678118654752f));
}

// EPI 0: qkv scatter, EPI 1: +bias +res, EPI 2: gelu(+bias)
template <int EPI>
__global__ void __launch_bounds__(256) gemm_kernel(
    const float* __restrict__ A, const float* __restrict__ B,
    int M, int N, int K, long long bstride,
    const float* __restrict__ bias, const float* __restrict__ res,
    float* __restrict__ out,
    float* __restrict__ oq, float* __restrict__ ok, float* __restrict__ ov) {
    __shared__ float As[16][128];
    __shared__ float Bs[16][128];
    int tid = threadIdx.x;
    int trow = tid >> 4, tcol = tid & 15;
    int bm = blockIdx.x << 7, bn = blockIdx.y << 7;
    const float* Bz = B + (long long)blockIdx.z * bstride;

    float acc[8][8];
#pragma unroll
    for (int i = 0; i < 8; i++)
#pragma unroll
        for (int j = 0; j < 8; j++) acc[i][j] = 0.f;

    int ar = tid >> 1, ac = (tid & 1) << 3;
    int br = tid >> 4, bc = (tid & 15) << 3;
    const float* Aptr = A + (size_t)(bm + ar) * K + ac;
    bool bvalid = (bn + bc) < N;

    for (int k0 = 0; k0 < K; k0 += 16) {
        float4 a0 = *(const float4*)(Aptr + k0);
        float4 a1 = *(const float4*)(Aptr + k0 + 4);
        As[ac + 0][ar] = a0.x; As[ac + 1][ar] = a0.y;
        As[ac + 2][ar] = a0.z; As[ac + 3][ar] = a0.w;
        As[ac + 4][ar] = a1.x; As[ac + 5][ar] = a1.y;
        As[ac + 6][ar] = a1.z; As[ac + 7][ar] = a1.w;
        if (bvalid) {
            const float* bp = Bz + (size_t)(k0 + br) * N + bn + bc;
            *(float4*)&Bs[br][bc] = *(const float4*)bp;
            *(float4*)&Bs[br][bc + 4] = *(const float4*)(bp + 4);
        } else {
            float4 z = make_float4(0.f, 0.f, 0.f, 0.f);
            *(float4*)&Bs[br][bc] = z;
            *(float4*)&Bs[br][bc + 4] = z;
        }
        __syncthreads();
#pragma unroll
        for (int k = 0; k < 16; k++) {
            float a[8], bf[8];
            *(float4*)a = *(float4*)&As[k][trow << 3];
            *(float4*)(a + 4) = *(float4*)&As[k][(trow << 3) + 4];
            *(float4*)bf = *(float4*)&Bs[k][tcol << 3];
            *(float4*)(bf + 4) = *(float4*)&Bs[k][(tcol << 3) + 4];
#pragma unroll
            for (int i = 0; i < 8; i++)
#pragma unroll
                for (int j = 0; j < 8; j++) acc[i][j] += a[i] * bf[j];
        }
        __syncthreads();
    }

#pragma unroll
    for (int i = 0; i < 8; i++) {
        int m = bm + (trow << 3) + i;
#pragma unroll
        for (int j = 0; j < 8; j++) {
            int n = bn + (tcol << 3) + j;
            if (n >= N) continue;
            float cval = acc[i][j];
            if (EPI == 0) {
                int which = n >> 6;
                int d = n & 63;
                int b_ = m >> 11;
                int s_ = m & 2047;
                int bh = (b_ << 4) + blockIdx.z;
                float* dst = (which == 0) ? oq : (which == 1) ? ok : ov;
                dst[((size_t)bh * S_SEQ + s_) * HD + d] = cval;
            } else if (EPI == 1) {
                out[(size_t)m * N + n] = cval + bias[n] + res[(size_t)m * N + n];
            } else {
                out[(size_t)m * N + n] = geluf(cval + bias[n]);
            }
        }
    }
}

// ---------------- Flash attention (64x64 tiles, fp32) ----------------
// Thread map: 256 threads, ty=tid/16 owns 4 query rows (ty*4+i),
// tx=tid%16 owns score cols (tx+16*j) and output dims (tx*4+c).
#define ATT_SMEM_FLOATS (4096 + 64 * 68 + 4096 + 4096)
__global__ void __launch_bounds__(256) attn_kernel(const float* __restrict__ Qg,
                                                   const float* __restrict__ Kg,
                                                   const float* __restrict__ Vg,
                                                   float* __restrict__ Og) {
    extern __shared__ float sm[];
    float* Qs = sm;              // 64 x 64
    float* Ks = sm + 4096;       // 64 x 68 (padded: avoids 8-way conflicts on col-major frag reads)
    float* Vs = Ks + 64 * 68;    // 64 x 64
    float* Ps = Vs + 4096;       // 64 x 64

    int tid = threadIdx.x;
    int tx = tid & 15, ty = tid >> 4;
    int q0 = blockIdx.x * 64;
    int bh = blockIdx.y;
    const float* qp = Qg + (size_t)bh * S_SEQ * HD;
    const float* kp = Kg + (size_t)bh * S_SEQ * HD;
    const float* vp = Vg + (size_t)bh * S_SEQ * HD;

#pragma unroll
    for (int j = 0; j < 4; j++) {
        int f = tid + 256 * j;
        int r = f >> 4, c4 = f & 15;
        *(float4*)&Qs[r * 64 + c4 * 4] = *(const float4*)&qp[(size_t)(q0 + r) * HD + c4 * 4];
    }

    float o[4][4];
    float mrow[4], lrow[4];
#pragma unroll
    for (int i = 0; i < 4; i++) {
        mrow[i] = -1e30f;
        lrow[i] = 0.f;
#pragma unroll
        for (int c = 0; c < 4; c++) o[i][c] = 0.f;
    }
    __syncthreads();

    const float scale = 0.125f;  // 64^-0.5
    for (int kt = 0; kt < S_SEQ / 64; kt++) {
        int kbase = kt * 64;
#pragma unroll
        for (int j = 0; j < 4; j++) {
            int f = tid + 256 * j;
            int r = f >> 4, c4 = f & 15;
            *(float4*)&Ks[r * 68 + c4 * 4] = *(const float4*)&kp[(size_t)(kbase + r) * HD + c4 * 4];
            *(float4*)&Vs[r * 64 + c4 * 4] = *(const float4*)&vp[(size_t)(kbase + r) * HD + c4 * 4];
        }
        __syncthreads();

        // S = scale * Q @ K^T
        float s[4][4];
#pragma unroll
        for (int i = 0; i < 4; i++)
#pragma unroll
            for (int j = 0; j < 4; j++) s[i][j] = 0.f;
#pragma unroll
        for (int d4 = 0; d4 < 16; d4++) {
            float4 qv[4], kv[4];
#pragma unroll
            for (int i = 0; i < 4; i++) qv[i] = *(float4*)&Qs[(ty * 4 + i) * 64 + d4 * 4];
#pragma unroll
            for (int j = 0; j < 4; j++) kv[j] = *(float4*)&Ks[(tx + 16 * j) * 68 + d4 * 4];
#pragma unroll
            for (int i = 0; i < 4; i++)
#pragma unroll
                for (int j = 0; j < 4; j++)
                    s[i][j] += qv[i].x * kv[j].x + qv[i].y * kv[j].y +
                               qv[i].z * kv[j].z + qv[i].w * kv[j].w;
        }

        // online softmax per row (reduction across 16 lanes of the row group)
#pragma unroll
        for (int i = 0; i < 4; i++) {
            float rm = -1e30f;
#pragma unroll
            for (int j = 0; j < 4; j++) { s[i][j] *= scale; rm = fmaxf(rm, s[i][j]); }
#pragma unroll
            for (int off = 8; off >= 1; off >>= 1)
                rm = fmaxf(rm, __shfl_xor_sync(0xffffffffu, rm, off));
            float mnew = fmaxf(mrow[i], rm);
            float corr = __expf(mrow[i] - mnew);
            float rs = 0.f;
#pragma unroll
            for (int j = 0; j < 4; j++) {
                float p = __expf(s[i][j] - mnew);
                s[i][j] = p;
                rs += p;
            }
#pragma unroll
            for (int off = 8; off >= 1; off >>= 1)
                rs += __shfl_xor_sync(0xffffffffu, rs, off);
            lrow[i] = lrow[i] * corr + rs;
            mrow[i] = mnew;
#pragma unroll
            for (int c = 0; c < 4; c++) o[i][c] *= corr;
#pragma unroll
            for (int j = 0; j < 4; j++) Ps[(ty * 4 + i) * 64 + tx + 16 * j] = s[i][j];
        }
        __syncthreads();

        // O += P @ V
#pragma unroll
        for (int j4 = 0; j4 < 16; j4++) {
            float4 vv[4];
#pragma unroll
            for (int jj = 0; jj < 4; jj++)
                vv[jj] = *(float4*)&Vs[(j4 * 4 + jj) * 64 + tx * 4];
#pragma unroll
            for (int i = 0; i < 4; i++) {
                float4 pv = *(float4*)&Ps[(ty * 4 + i) * 64 + j4 * 4];
                o[i][0] += pv.x * vv[0].x + pv.y * vv[1].x + pv.z * vv[2].x + pv.w * vv[3].x;
                o[i][1] += pv.x * vv[0].y + pv.y * vv[1].y + pv.z * vv[2].y + pv.w * vv[3].y;
                o[i][2] += pv.x * vv[0].z + pv.y * vv[1].z + pv.z * vv[2].z + pv.w * vv[3].z;
                o[i][3] += pv.x * vv[0].w + pv.y * vv[1].w + pv.z * vv[2].w + pv.w * vv[3].w;
            }
        }
        __syncthreads();
    }

    // write to concat-head layout g_o[token][h*64 + d]
    int b_ = bh >> 4, h = bh & 15;
#pragma unroll
    for (int i = 0; i < 4; i++) {
        int srow = q0 + ty * 4 + i;
        size_t t = (size_t)b_ * S_SEQ + srow;
        float inv = 1.0f / lrow[i];
        float4 r;
        r.x = o[i][0] * inv; r.y = o[i][1] * inv;
        r.z = o[i][2] * inv; r.w = o[i][3] * inv;
        *(float4*)&Og[t * D_EMB + h * HD + tx * 4] = r;
    }
}

// ---------------- launch ----------------
extern "C" void kernel_launch(void* const* d_in, const int* in_sizes, int n_in,
                              void* d_out, int out_size) {
    const float* x = (const float*)d_in[0];
    const float* w_qkv = (const float*)d_in[1];
    const float* w_hproj = (const float*)d_in[2];
    const float* b_hproj = (const float*)d_in[3];
    const float* w_out = (const float*)d_in[4];
    const float* b_out = (const float*)d_in[5];
    const float* w_fc1 = (const float*)d_in[6];
    const float* b_fc1 = (const float*)d_in[7];
    const float* w_fc2 = (const float*)d_in[8];
    const float* b_fc2 = (const float*)d_in[9];
    const float* g1 = (const float*)d_in[10];
    const float* be1 = (const float*)d_in[11];
    const float* g2 = (const float*)d_in[12];
    const float* be2 = (const float*)d_in[13];
    float* out = (float*)d_out;

    float *xn, *q, *k, *v, *o, *x1, *hb, *W2, *b2;
    cudaGetSymbolAddress((void**)&xn, g_xn);
    cudaGetSymbolAddress((void**)&q, g_q);
    cudaGetSymbolAddress((void**)&k, g_k);
    cudaGetSymbolAddress((void**)&v, g_v);
    cudaGetSymbolAddress((void**)&o, g_o);
    cudaGetSymbolAddress((void**)&x1, g_x1);
    cudaGetSymbolAddress((void**)&hb, g_h);
    cudaGetSymbolAddress((void**)&W2, g_W2);
    cudaGetSymbolAddress((void**)&b2, g_b2);

    cudaFuncSetAttribute(attn_kernel, cudaFuncAttributeMaxDynamicSharedMemorySize,
                         ATT_SMEM_FLOATS * 4);

    // LN1
    ln_kernel<<<T_TOK, 256>>>(x, g1, be1, xn);
    // fused projection weight/bias (independent of LN)
    fuse_w2_kernel<<<dim3(16, 16), 256>>>(w_hproj, w_out, W2);
    bias2_kernel<<<4, 256>>>(b_hproj, b_out, w_out, b2);
    // QKV: per-head GEMM [4096,1024]x[1024,192], scatter to q/k/v
    gemm_kernel<0><<<dim3(32, 2, 16), 256>>>(xn, w_qkv, T_TOK, 192, D_EMB,
                                             (long long)D_EMB * 192,
                                             nullptr, nullptr, nullptr, q, k, v);
    // flash attention -> concat-head layout
    attn_kernel<<<dim3(S_SEQ / 64, 32), 256, ATT_SMEM_FLOATS * 4>>>(q, k, v, o);
    // out projection (fused hproj+wout) + bias2 + residual x -> x1
    gemm_kernel<1><<<dim3(32, 8), 256>>>(o, W2, T_TOK, D_EMB, D_EMB, 0,
                                         b2, x, x1, nullptr, nullptr, nullptr);
    // LN2
    ln_kernel<<<T_TOK, 256>>>(x1, g2, be2, xn);
    // FC1 + bias + exact GELU
    gemm_kernel<2><<<dim3(32, 32), 256>>>(xn, w_fc1, T_TOK, MLP_DIM, D_EMB, 0,
                                          b_fc1, nullptr, hb, nullptr, nullptr, nullptr);
    // FC2 + bias + residual x1 -> out
    gemm_kernel<1><<<dim3(32, 8), 256>>>(hb, w_fc2, T_TOK, D_EMB, MLP_DIM, 0,
                                         b_fc2, x1, out, nullptr, nullptr, nullptr);
}

// round 2
// speedup vs baseline: 2.0551x; 2.0551x over previous
#include <cuda_runtime.h>
#include <math.h>

#define T_TOK 4096
#define D_EMB 1024
#define S_SEQ 2048
#define NH 16
#define HD 64
#define MLP_DIM 4096

// -------- scratch (device globals; no allocation allowed) --------
__device__ float g_xn[T_TOK * D_EMB];
__device__ float g_q[32 * S_SEQ * HD];
__device__ float g_k[32 * S_SEQ * HD];
__device__ float g_v[32 * S_SEQ * HD];
__device__ float g_o[T_TOK * D_EMB];
__device__ float g_x1[T_TOK * D_EMB];
__device__ float g_h[T_TOK * MLP_DIM];
__device__ float g_W2[D_EMB * D_EMB];
__device__ float g_b2[D_EMB];
__device__ float g_wqkvp[D_EMB * 3 * HD * NH];  // [1024][3072] packed

// ---------------- LayerNorm: one block per row of 1024 ----------------
__global__ void __launch_bounds__(256) ln_kernel(const float* __restrict__ in,
                                                 const float* __restrict__ g,
                                                 const float* __restrict__ b,
                                                 float* __restrict__ out) {
    __shared__ float s_sum[256], s_sq[256];
    int row = blockIdx.x, tid = threadIdx.x;
    float4 v = ((const float4*)(in + (size_t)row * D_EMB))[tid];
    s_sum[tid] = v.x + v.y + v.z + v.w;
    s_sq[tid] = v.x * v.x + v.y * v.y + v.z * v.z + v.w * v.w;
    __syncthreads();
    for (int s = 128; s > 0; s >>= 1) {
        if (tid < s) { s_sum[tid] += s_sum[tid + s]; s_sq[tid] += s_sq[tid + s]; }
        __syncthreads();
    }
    float mean = s_sum[0] * (1.0f / D_EMB);
    float var = s_sq[0] * (1.0f / D_EMB) - mean * mean;
    float inv = rsqrtf(var + 1e-5f);
    float4 gg = ((const float4*)g)[tid];
    float4 bb = ((const float4*)b)[tid];
    float4 r;
    r.x = (v.x - mean) * inv * gg.x + bb.x;
    r.y = (v.y - mean) * inv * gg.y + bb.y;
    r.z = (v.z - mean) * inv * gg.z + bb.z;
    r.w = (v.w - mean) * inv * gg.w + bb.w;
    ((float4*)(out + (size_t)row * D_EMB))[tid] = r;
}

// ---------------- pack w_qkv [H][D][192] -> [D][H*192] ----------------
__global__ void __launch_bounds__(256) repack_qkv_kernel(const float* __restrict__ w,
                                                         float* __restrict__ wp) {
    int i = blockIdx.x * 256 + threadIdx.x;  // float4 index, total 786432
    int n4 = i % 768, d = i / 768;
    int n = n4 * 4;
    int h = n / 192, f = n - h * 192;
    float4 v = *(const float4*)&w[((size_t)h * D_EMB + d) * 192 + f];
    *(float4*)&wp[(size_t)d * 3072 + n] = v;
}

// ---------------- Fuse W2 = blockdiag(w_hproj) @ w_out ----------------
__global__ void __launch_bounds__(256) fuse_w2_kernel(const float* __restrict__ whp,
                                                      const float* __restrict__ wout,
                                                      float* __restrict__ W2) {
    __shared__ float hp[64 * 64];
    __shared__ float wo[64 * 64];
    int h = blockIdx.x, nt = blockIdx.y, tid = threadIdx.x;
#pragma unroll
    for (int j = 0; j < 4; j++) {
        int f = tid + 256 * j;
        ((float4*)hp)[f] = ((const float4*)(whp + (size_t)h * 4096))[f];
        int r = f >> 4, c4 = f & 15;
        *(float4*)&wo[r * 64 + c4 * 4] =
            *(const float4*)&wout[(size_t)(h * 64 + r) * D_EMB + nt * 64 + c4 * 4];
    }
    __syncthreads();
    int ty = tid >> 4, tx = tid & 15;
#pragma unroll
    for (int i = 0; i < 4; i++) {
        int d = ty * 4 + i;
#pragma unroll
        for (int j = 0; j < 4; j++) {
            int e = tx * 4 + j;
            float acc = 0.f;
#pragma unroll 8
            for (int k = 0; k < 64; k++) acc += hp[d * 64 + k] * wo[k * 64 + e];
            W2[(size_t)(h * 64 + d) * D_EMB + nt * 64 + e] = acc;
        }
    }
}

__global__ void __launch_bounds__(256) bias2_kernel(const float* __restrict__ bhp,
                                                    const float* __restrict__ bout,
                                                    const float* __restrict__ wout,
                                                    float* __restrict__ b2) {
    int e = blockIdx.x * 256 + threadIdx.x;
    float acc = bout[e];
    for (int i = 0; i < D_EMB; i++) acc += bhp[i] * wout[(size_t)i * D_EMB + e];
    b2[e] = acc;
}

// ---------------- tf32 tensor-core GEMM 128x128x16 ----------------
__device__ __forceinline__ float geluf(float x) {
    return 0.5f * x * (1.0f + erff(x * 0.70710678118654752f));
}
__device__ __forceinline__ unsigned f2tf(float x) {
    unsigned u;
    asm("cvt.rna.tf32.f32 %0, %1;" : "=r"(u) : "f"(x));
    return u;
}
__device__ __forceinline__ void cpasync16(float* s, const float* g) {
    unsigned sa = (unsigned)__cvta_generic_to_shared(s);
    asm volatile("cp.async.cg.shared.global [%0], [%1], 16;" :: "r"(sa), "l"(g));
}
__device__ __forceinline__ void cpcommit() { asm volatile("cp.async.commit_group;"); }
__device__ __forceinline__ void cpwait0() { asm volatile("cp.async.wait_group 0;"); }
__device__ __forceinline__ void cpwait1() { asm volatile("cp.async.wait_group 1;"); }

__device__ __forceinline__ void mma8(float* d, const unsigned* a, const unsigned* b) {
    asm volatile(
        "mma.sync.aligned.m16n8k8.row.col.f32.tf32.tf32.f32 "
        "{%0,%1,%2,%3},{%4,%5,%6,%7},{%8,%9},{%0,%1,%2,%3};"
        : "+f"(d[0]), "+f"(d[1]), "+f"(d[2]), "+f"(d[3])
        : "r"(a[0]), "r"(a[1]), "r"(a[2]), "r"(a[3]), "r"(b[0]), "r"(b[1]));
}

#define BM 128
#define BN 128
#define BK 16

// EPI 0: qkv scatter (N=3072), EPI 1: +bias +res, EPI 2: gelu(+bias)
// All M % 128 == 0, N % 128 == 0, K % 16 == 0 for every call site.
template <int EPI>
__global__ void __launch_bounds__(256, 2) gemm_tc(
    const float* __restrict__ A, const float* __restrict__ B,
    int M, int N, int K,
    const float* __restrict__ bias, const float* __restrict__ res,
    float* __restrict__ out,
    float* __restrict__ oq, float* __restrict__ okk, float* __restrict__ ov) {
    __shared__ float As[2][BM][20];
    __shared__ float Bs[2][BK][136];
    int tid = threadIdx.x;
    int lane = tid & 31, warp = tid >> 5;
    int wm = (warp >> 2) * 64, wn = (warp & 3) * 32;
    int bm = blockIdx.x * BM, bn = blockIdx.y * BN;

    float acc[4][4][4];
#pragma unroll
    for (int mi = 0; mi < 4; mi++)
#pragma unroll
        for (int ni = 0; ni < 4; ni++)
#pragma unroll
            for (int q = 0; q < 4; q++) acc[mi][ni][q] = 0.f;

    const float* Ag = A + (size_t)bm * K;
    const float* Bg = B + bn;
    // A tile: 128x16 = 512 float4; B tile: 16x128 = 512 float4; 2 per thread each
    int a_row0 = tid >> 2, a_kc = (tid & 3) << 2;
    int b_row0 = tid >> 5, b_nc = (tid & 31) << 2;

    // prologue: stage 0
    {
        cpasync16(&As[0][a_row0][a_kc], Ag + (size_t)a_row0 * K + a_kc);
        cpasync16(&As[0][a_row0 + 64][a_kc], Ag + (size_t)(a_row0 + 64) * K + a_kc);
        cpasync16(&Bs[0][b_row0][b_nc], Bg + (size_t)b_row0 * N + b_nc);
        cpasync16(&Bs[0][b_row0 + 8][b_nc], Bg + (size_t)(b_row0 + 8) * N + b_nc);
        cpcommit();
    }

    int T = K / BK;
    int r = lane >> 2, c = lane & 3;
    for (int t = 0; t < T; t++) {
        int buf = t & 1;
        if (t + 1 < T) {
            int k0 = (t + 1) * BK;
            int nb = 1 - buf;
            cpasync16(&As[nb][a_row0][a_kc], Ag + (size_t)a_row0 * K + k0 + a_kc);
            cpasync16(&As[nb][a_row0 + 64][a_kc], Ag + (size_t)(a_row0 + 64) * K + k0 + a_kc);
            cpasync16(&Bs[nb][b_row0][b_nc], Bg + (size_t)(k0 + b_row0) * N + b_nc);
            cpasync16(&Bs[nb][b_row0 + 8][b_nc], Bg + (size_t)(k0 + b_row0 + 8) * N + b_nc);
            cpcommit();
            cpwait1();
        } else {
            cpwait0();
        }
        __syncthreads();

#pragma unroll
        for (int ks = 0; ks < 2; ks++) {
            int kk = ks * 8;
            unsigned a[4][4], bfr[4][2];
#pragma unroll
            for (int mi = 0; mi < 4; mi++) {
                int m0 = wm + mi * 16 + r;
                a[mi][0] = f2tf(As[buf][m0][kk + c]);
                a[mi][1] = f2tf(As[buf][m0 + 8][kk + c]);
                a[mi][2] = f2tf(As[buf][m0][kk + 4 + c]);
                a[mi][3] = f2tf(As[buf][m0 + 8][kk + 4 + c]);
            }
#pragma unroll
            for (int ni = 0; ni < 4; ni++) {
                int n0 = wn + ni * 8 + r;
                bfr[ni][0] = f2tf(Bs[buf][kk + c][n0]);
                bfr[ni][1] = f2tf(Bs[buf][kk + 4 + c][n0]);
            }
#pragma unroll
            for (int mi = 0; mi < 4; mi++)
#pragma unroll
                for (int ni = 0; ni < 4; ni++) mma8(acc[mi][ni], a[mi], bfr[ni]);
        }
        __syncthreads();
    }

    // epilogue
    int c2 = (lane & 3) * 2;
#pragma unroll
    for (int mi = 0; mi < 4; mi++) {
        int row0 = bm + wm + mi * 16 + r;
        int row1 = row0 + 8;
#pragma unroll
        for (int ni = 0; ni < 4; ni++) {
            int col = bn + wn + ni * 8 + c2;
            float v00 = acc[mi][ni][0], v01 = acc[mi][ni][1];
            float v10 = acc[mi][ni][2], v11 = acc[mi][ni][3];
            if (EPI == 0) {
                int h = col / 192;
                int f = col - h * 192;
                int which = f >> 6;
                int d = f & 63;
                float* dst = (which == 0) ? oq : (which == 1) ? okk : ov;
                {
                    int b_ = row0 >> 11, s_ = row0 & 2047;
                    size_t base = (((size_t)(b_ * 16 + h) * S_SEQ + s_) * HD + d);
                    dst[base] = v00;
                    dst[base + 1] = v01;
                }
                {
                    int b_ = row1 >> 11, s_ = row1 & 2047;
                    size_t base = (((size_t)(b_ * 16 + h) * S_SEQ + s_) * HD + d);
                    dst[base] = v10;
                    dst[base + 1] = v11;
                }
            } else if (EPI == 1) {
                float2 bv = *(const float2*)&bias[col];
                float2 r0 = *(const float2*)&res[(size_t)row0 * N + col];
                float2 r1 = *(const float2*)&res[(size_t)row1 * N + col];
                float2 o0, o1;
                o0.x = v00 + bv.x + r0.x; o0.y = v01 + bv.y + r0.y;
                o1.x = v10 + bv.x + r1.x; o1.y = v11 + bv.y + r1.y;
                *(float2*)&out[(size_t)row0 * N + col] = o0;
                *(float2*)&out[(size_t)row1 * N + col] = o1;
            } else {
                float2 bv = *(const float2*)&bias[col];
                float2 o0, o1;
                o0.x = geluf(v00 + bv.x); o0.y = geluf(v01 + bv.y);
                o1.x = geluf(v10 + bv.x); o1.y = geluf(v11 + bv.y);
                *(float2*)&out[(size_t)row0 * N + col] = o0;
                *(float2*)&out[(size_t)row1 * N + col] = o1;
            }
        }
    }
}

// ---------------- Flash attention (64x64 tiles, fp32) ----------------
#define ATT_SMEM_FLOATS (4096 + 64 * 68 + 4096 + 4096)
__global__ void __launch_bounds__(256) attn_kernel(const float* __restrict__ Qg,
                                                   const float* __restrict__ Kg,
                                                   const float* __restrict__ Vg,
                                                   float* __restrict__ Og) {
    extern __shared__ float sm[];
    float* Qs = sm;
    float* Ks = sm + 4096;
    float* Vs = Ks + 64 * 68;
    float* Ps = Vs + 4096;

    int tid = threadIdx.x;
    int tx = tid & 15, ty = tid >> 4;
    int q0 = blockIdx.x * 64;
    int bh = blockIdx.y;
    const float* qp = Qg + (size_t)bh * S_SEQ * HD;
    const float* kp = Kg + (size_t)bh * S_SEQ * HD;
    const float* vp = Vg + (size_t)bh * S_SEQ * HD;

#pragma unroll
    for (int j = 0; j < 4; j++) {
        int f = tid + 256 * j;
        int r = f >> 4, c4 = f & 15;
        *(float4*)&Qs[r * 64 + c4 * 4] = *(const float4*)&qp[(size_t)(q0 + r) * HD + c4 * 4];
    }

    float o[4][4];
    float mrow[4], lrow[4];
#pragma unroll
    for (int i = 0; i < 4; i++) {
        mrow[i] = -1e30f;
        lrow[i] = 0.f;
#pragma unroll
        for (int c = 0; c < 4; c++) o[i][c] = 0.f;
    }
    __syncthreads();

    const float scale = 0.125f;
    for (int kt = 0; kt < S_SEQ / 64; kt++) {
        int kbase = kt * 64;
#pragma unroll
        for (int j = 0; j < 4; j++) {
            int f = tid + 256 * j;
            int r = f >> 4, c4 = f & 15;
            *(float4*)&Ks[r * 68 + c4 * 4] = *(const float4*)&kp[(size_t)(kbase + r) * HD + c4 * 4];
            *(float4*)&Vs[r * 64 + c4 * 4] = *(const float4*)&vp[(size_t)(kbase + r) * HD + c4 * 4];
        }
        __syncthreads();

        float s[4][4];
#pragma unroll
        for (int i = 0; i < 4; i++)
#pragma unroll
            for (int j = 0; j < 4; j++) s[i][j] = 0.f;
#pragma unroll
        for (int d4 = 0; d4 < 16; d4++) {
            float4 qv[4], kv[4];
#pragma unroll
            for (int i = 0; i < 4; i++) qv[i] = *(float4*)&Qs[(ty * 4 + i) * 64 + d4 * 4];
#pragma unroll
            for (int j = 0; j < 4; j++) kv[j] = *(float4*)&Ks[(tx + 16 * j) * 68 + d4 * 4];
#pragma unroll
            for (int i = 0; i < 4; i++)
#pragma unroll
                for (int j = 0; j < 4; j++)
                    s[i][j] += qv[i].x * kv[j].x + qv[i].y * kv[j].y +
                               qv[i].z * kv[j].z + qv[i].w * kv[j].w;
        }

#pragma unroll
        for (int i = 0; i < 4; i++) {
            float rm = -1e30f;
#pragma unroll
            for (int j = 0; j < 4; j++) { s[i][j] *= scale; rm = fmaxf(rm, s[i][j]); }
#pragma unroll
            for (int off = 8; off >= 1; off >>= 1)
                rm = fmaxf(rm, __shfl_xor_sync(0xffffffffu, rm, off));
            float mnew = fmaxf(mrow[i], rm);
            float corr = __expf(mrow[i] - mnew);
            float rs = 0.f;
#pragma unroll
            for (int j = 0; j < 4; j++) {
                float p = __expf(s[i][j] - mnew);
                s[i][j] = p;
                rs += p;
            }
#pragma unroll
            for (int off = 8; off >= 1; off >>= 1)
                rs += __shfl_xor_sync(0xffffffffu, rs, off);
            lrow[i] = lrow[i] * corr + rs;
            mrow[i] = mnew;
#pragma unroll
            for (int c = 0; c < 4; c++) o[i][c] *= corr;
#pragma unroll
            for (int j = 0; j < 4; j++) Ps[(ty * 4 + i) * 64 + tx + 16 * j] = s[i][j];
        }
        __syncthreads();

#pragma unroll
        for (int j4 = 0; j4 < 16; j4++) {
            float4 vv[4];
#pragma unroll
            for (int jj = 0; jj < 4; jj++)
                vv[jj] = *(float4*)&Vs[(j4 * 4 + jj) * 64 + tx * 4];
#pragma unroll
            for (int i = 0; i < 4; i++) {
                float4 pv = *(float4*)&Ps[(ty * 4 + i) * 64 + j4 * 4];
                o[i][0] += pv.x * vv[0].x + pv.y * vv[1].x + pv.z * vv[2].x + pv.w * vv[3].x;
                o[i][1] += pv.x * vv[0].y + pv.y * vv[1].y + pv.z * vv[2].y + pv.w * vv[3].y;
                o[i][2] += pv.x * vv[0].z + pv.y * vv[1].z + pv.z * vv[2].z + pv.w * vv[3].z;
                o[i][3] += pv.x * vv[0].w + pv.y * vv[1].w + pv.z * vv[2].w + pv.w * vv[3].w;
            }
        }
        __syncthreads();
    }

    int b_ = bh >> 4, h = bh & 15;
#pragma unroll
    for (int i = 0; i < 4; i++) {
        int srow = q0 + ty * 4 + i;
        size_t t = (size_t)b_ * S_SEQ + srow;
        float inv = 1.0f / lrow[i];
        float4 rr;
        rr.x = o[i][0] * inv; rr.y = o[i][1] * inv;
        rr.z = o[i][2] * inv; rr.w = o[i][3] * inv;
        *(float4*)&Og[t * D_EMB + h * HD + tx * 4] = rr;
    }
}

// ---------------- launch ----------------
extern "C" void kernel_launch(void* const* d_in, const int* in_sizes, int n_in,
                              void* d_out, int out_size) {
    const float* x = (const float*)d_in[0];
    const float* w_qkv = (const float*)d_in[1];
    const float* w_hproj = (const float*)d_in[2];
    const float* b_hproj = (const float*)d_in[3];
    const float* w_out = (const float*)d_in[4];
    const float* b_out = (const float*)d_in[5];
    const float* w_fc1 = (const float*)d_in[6];
    const float* b_fc1 = (const float*)d_in[7];
    const float* w_fc2 = (const float*)d_in[8];
    const float* b_fc2 = (const float*)d_in[9];
    const float* g1 = (const float*)d_in[10];
    const float* be1 = (const float*)d_in[11];
    const float* g2 = (const float*)d_in[12];
    const float* be2 = (const float*)d_in[13];
    float* out = (float*)d_out;

    float *xn, *q, *k, *v, *o, *x1, *hb, *W2, *b2, *wqkvp;
    cudaGetSymbolAddress((void**)&xn, g_xn);
    cudaGetSymbolAddress((void**)&q, g_q);
    cudaGetSymbolAddress((void**)&k, g_k);
    cudaGetSymbolAddress((void**)&v, g_v);
    cudaGetSymbolAddress((void**)&o, g_o);
    cudaGetSymbolAddress((void**)&x1, g_x1);
    cudaGetSymbolAddress((void**)&hb, g_h);
    cudaGetSymbolAddress((void**)&W2, g_W2);
    cudaGetSymbolAddress((void**)&b2, g_b2);
    cudaGetSymbolAddress((void**)&wqkvp, g_wqkvp);

    cudaFuncSetAttribute(attn_kernel, cudaFuncAttributeMaxDynamicSharedMemorySize,
                         ATT_SMEM_FLOATS * 4);

    // LN1 + weight prep (independent)
    ln_kernel<<<T_TOK, 256>>>(x, g1, be1, xn);
    repack_qkv_kernel<<<3072, 256>>>(w_qkv, wqkvp);
    fuse_w2_kernel<<<dim3(16, 16), 256>>>(w_hproj, w_out, W2);
    bias2_kernel<<<4, 256>>>(b_hproj, b_out, w_out, b2);
    // QKV: [4096,1024] x [1024,3072], scatter to q/k/v head layout
    gemm_tc<0><<<dim3(32, 24), 256>>>(xn, wqkvp, T_TOK, 3072, D_EMB,
                                      nullptr, nullptr, nullptr, q, k, v);
    // flash attention -> concat-head layout
    attn_kernel<<<dim3(S_SEQ / 64, 32), 256, ATT_SMEM_FLOATS * 4>>>(q, k, v, o);
    // out projection (fused hproj+wout) + bias2 + residual -> x1
    gemm_tc<1><<<dim3(32, 8), 256>>>(o, W2, T_TOK, D_EMB, D_EMB,
                                     b2, x, x1, nullptr, nullptr, nullptr);
    // LN2
    ln_kernel<<<T_TOK, 256>>>(x1, g2, be2, xn);
    // FC1 + bias + exact GELU
    gemm_tc<2><<<dim3(32, 32), 256>>>(xn, w_fc1, T_TOK, MLP_DIM, D_EMB,
                                      b_fc1, nullptr, hb, nullptr, nullptr, nullptr);
    // FC2 + bias + residual x1 -> out
    gemm_tc<1><<<dim3(32, 8), 256>>>(hb, w_fc2, T_TOK, D_EMB, MLP_DIM,
                                     b_fc2, x1, out, nullptr, nullptr, nullptr);
}

// round 4
// speedup vs baseline: 3.2772x; 1.5947x over previous
#include <cuda_runtime.h>
#include <math.h>

#define T_TOK 4096
#define D_EMB 1024
#define S_SEQ 2048
#define NH 16
#define HD 64
#define MLP_DIM 4096

// -------- scratch (device globals; no allocation allowed) --------
__device__ float g_xn[T_TOK * D_EMB];
__device__ float g_q[32 * S_SEQ * HD];
__device__ float g_k[32 * S_SEQ * HD];
__device__ float g_v[32 * S_SEQ * HD];
__device__ float g_o[T_TOK * D_EMB];
__device__ float g_x1[T_TOK * D_EMB];
__device__ float g_h[T_TOK * MLP_DIM];
__device__ float g_W2[D_EMB * D_EMB];
__device__ float g_b2[D_EMB];
__device__ float g_wqkvp[D_EMB * 3 * HD * NH];  // [1024][3072] packed

// ---------------- helpers ----------------
__device__ __forceinline__ unsigned f2tf(float x) {
    unsigned u;
    asm("cvt.rna.tf32.f32 %0, %1;" : "=r"(u) : "f"(x));
    return u;
}
__device__ __forceinline__ float tfr(float x) { return __uint_as_float(f2tf(x)); }
__device__ __forceinline__ float geluf(float x) {
    return 0.5f * x * (1.0f + erff(x * 0.70710678118654752f));
}
__device__ __forceinline__ void cpasync16(float* s, const float* g) {
    unsigned sa = (unsigned)__cvta_generic_to_shared(s);
    asm volatile("cp.async.cg.shared.global [%0], [%1], 16;" :: "r"(sa), "l"(g));
}
__device__ __forceinline__ void cpcommit() { asm volatile("cp.async.commit_group;"); }
__device__ __forceinline__ void cpwait0() { asm volatile("cp.async.wait_group 0;"); }
__device__ __forceinline__ void cpwait1() { asm volatile("cp.async.wait_group 1;"); }
__device__ __forceinline__ void mma8(float* d, const unsigned* a, const unsigned* b) {
    asm volatile(
        "mma.sync.aligned.m16n8k8.row.col.f32.tf32.tf32.f32 "
        "{%0,%1,%2,%3},{%4,%5,%6,%7},{%8,%9},{%0,%1,%2,%3};"
        : "+f"(d[0]), "+f"(d[1]), "+f"(d[2]), "+f"(d[3])
        : "r"(a[0]), "r"(a[1]), "r"(a[2]), "r"(a[3]), "r"(b[0]), "r"(b[1]));
}

// ---------------- LayerNorm (rounds output to tf32 for GEMM A use) ----------------
__global__ void __launch_bounds__(256) ln_kernel(const float* __restrict__ in,
                                                 const float* __restrict__ g,
                                                 const float* __restrict__ b,
                                                 float* __restrict__ out) {
    __shared__ float s_sum[256], s_sq[256];
    int row = blockIdx.x, tid = threadIdx.x;
    float4 v = ((const float4*)(in + (size_t)row * D_EMB))[tid];
    s_sum[tid] = v.x + v.y + v.z + v.w;
    s_sq[tid] = v.x * v.x + v.y * v.y + v.z * v.z + v.w * v.w;
    __syncthreads();
    for (int s = 128; s > 0; s >>= 1) {
        if (tid < s) { s_sum[tid] += s_sum[tid + s]; s_sq[tid] += s_sq[tid + s]; }
        __syncthreads();
    }
    float mean = s_sum[0] * (1.0f / D_EMB);
    float var = s_sq[0] * (1.0f / D_EMB) - mean * mean;
    float inv = rsqrtf(var + 1e-5f);
    float4 gg = ((const float4*)g)[tid];
    float4 bb = ((const float4*)b)[tid];
    float4 r;
    r.x = tfr((v.x - mean) * inv * gg.x + bb.x);
    r.y = tfr((v.y - mean) * inv * gg.y + bb.y);
    r.z = tfr((v.z - mean) * inv * gg.z + bb.z);
    r.w = tfr((v.w - mean) * inv * gg.w + bb.w);
    ((float4*)(out + (size_t)row * D_EMB))[tid] = r;
}

// ---------------- pack w_qkv [H][D][192] -> [D][H*192], tf32-rounded ----------------
__global__ void __launch_bounds__(256) repack_qkv_kernel(const float* __restrict__ w,
                                                         float* __restrict__ wp) {
    int i = blockIdx.x * 256 + threadIdx.x;
    int n4 = i % 768, d = i / 768;
    int n = n4 * 4;
    int h = n / 192, f = n - h * 192;
    float4 v = *(const float4*)&w[((size_t)h * D_EMB + d) * 192 + f];
    v.x = tfr(v.x); v.y = tfr(v.y); v.z = tfr(v.z); v.w = tfr(v.w);
    *(float4*)&wp[(size_t)d * 3072 + n] = v;
}

// ---------------- Fuse W2 = blockdiag(w_hproj) @ w_out (tf32-rounded) ----------------
__global__ void __launch_bounds__(256) fuse_w2_kernel(const float* __restrict__ whp,
                                                      const float* __restrict__ wout,
                                                      float* __restrict__ W2) {
    __shared__ float hp[64 * 64];
    __shared__ float wo[64 * 64];
    int h = blockIdx.x, nt = blockIdx.y, tid = threadIdx.x;
#pragma unroll
    for (int j = 0; j < 4; j++) {
        int f = tid + 256 * j;
        ((float4*)hp)[f] = ((const float4*)(whp + (size_t)h * 4096))[f];
        int r = f >> 4, c4 = f & 15;
        *(float4*)&wo[r * 64 + c4 * 4] =
            *(const float4*)&wout[(size_t)(h * 64 + r) * D_EMB + nt * 64 + c4 * 4];
    }
    __syncthreads();
    int ty = tid >> 4, tx = tid & 15;
#pragma unroll
    for (int i = 0; i < 4; i++) {
        int d = ty * 4 + i;
#pragma unroll
        for (int j = 0; j < 4; j++) {
            int e = tx * 4 + j;
            float acc = 0.f;
#pragma unroll 8
            for (int k = 0; k < 64; k++) acc += hp[d * 64 + k] * wo[k * 64 + e];
            W2[(size_t)(h * 64 + d) * D_EMB + nt * 64 + e] = tfr(acc);
        }
    }
}

// bias2[e] = b_out[e] + sum_i b_hproj_flat[i] * w_out[i][e]
__global__ void __launch_bounds__(256) bias2_kernel(const float* __restrict__ bhp,
                                                    const float* __restrict__ bout,
                                                    const float* __restrict__ wout,
                                                    float* __restrict__ b2) {
    __shared__ float part[4][64];
    int tid = threadIdx.x;
    int e = blockIdx.x * 64 + (tid & 63);
    int chunk = tid >> 6;
    float acc = 0.f;
    int i0 = chunk * 256;
    for (int i = i0; i < i0 + 256; i++) acc += bhp[i] * wout[(size_t)i * D_EMB + e];
    part[chunk][tid & 63] = acc;
    __syncthreads();
    if (chunk == 0)
        b2[e] = bout[e] + part[0][tid] + part[1][tid] + part[2][tid] + part[3][tid];
}

// ---------------- tf32 tensor-core GEMM 128x128x16 ----------------
#define BM 128
#define BN 128
#define BK 16

// EPI 0: qkv scatter (rounded), EPI 1: +bias +res (full fp32), EPI 2: gelu+bias (rounded)
// A operands are always pre-rounded to tf32; B frags cvt only when CVTB.
template <int EPI, bool CVTB>
__global__ void __launch_bounds__(256, 2) gemm_tc(
    const float* __restrict__ A, const float* __restrict__ B,
    int M, int N, int K,
    const float* __restrict__ bias, const float* __restrict__ res,
    float* __restrict__ out,
    float* __restrict__ oq, float* __restrict__ okk, float* __restrict__ ov) {
    __shared__ float As[2][BM][20];
    __shared__ float Bs[2][BK][136];
    int tid = threadIdx.x;
    int lane = tid & 31, warp = tid >> 5;
    int wm = (warp >> 2) * 64, wn = (warp & 3) * 32;
    int bm = blockIdx.x * BM, bn = blockIdx.y * BN;

    float acc[4][4][4];
#pragma unroll
    for (int mi = 0; mi < 4; mi++)
#pragma unroll
        for (int ni = 0; ni < 4; ni++)
#pragma unroll
            for (int q = 0; q < 4; q++) acc[mi][ni][q] = 0.f;

    const float* Ag = A + (size_t)bm * K;
    const float* Bg = B + bn;
    int a_row0 = tid >> 2, a_kc = (tid & 3) << 2;
    int b_row0 = tid >> 5, b_nc = (tid & 31) << 2;

    {
        cpasync16(&As[0][a_row0][a_kc], Ag + (size_t)a_row0 * K + a_kc);
        cpasync16(&As[0][a_row0 + 64][a_kc], Ag + (size_t)(a_row0 + 64) * K + a_kc);
        cpasync16(&Bs[0][b_row0][b_nc], Bg + (size_t)b_row0 * N + b_nc);
        cpasync16(&Bs[0][b_row0 + 8][b_nc], Bg + (size_t)(b_row0 + 8) * N + b_nc);
        cpcommit();
    }

    int T = K / BK;
    int r = lane >> 2, c = lane & 3;
    for (int t = 0; t < T; t++) {
        int buf = t & 1;
        if (t + 1 < T) {
            int k0 = (t + 1) * BK;
            int nb = 1 - buf;
            cpasync16(&As[nb][a_row0][a_kc], Ag + (size_t)a_row0 * K + k0 + a_kc);
            cpasync16(&As[nb][a_row0 + 64][a_kc], Ag + (size_t)(a_row0 + 64) * K + k0 + a_kc);
            cpasync16(&Bs[nb][b_row0][b_nc], Bg + (size_t)(k0 + b_row0) * N + b_nc);
            cpasync16(&Bs[nb][b_row0 + 8][b_nc], Bg + (size_t)(k0 + b_row0 + 8) * N + b_nc);
            cpcommit();
            cpwait1();
        } else {
            cpwait0();
        }
        __syncthreads();

#pragma unroll
        for (int ks = 0; ks < 2; ks++) {
            int kk = ks * 8;
            unsigned a[4][4], bfr[4][2];
#pragma unroll
            for (int mi = 0; mi < 4; mi++) {
                int m0 = wm + mi * 16 + r;
                a[mi][0] = __float_as_uint(As[buf][m0][kk + c]);
                a[mi][1] = __float_as_uint(As[buf][m0 + 8][kk + c]);
                a[mi][2] = __float_as_uint(As[buf][m0][kk + 4 + c]);
                a[mi][3] = __float_as_uint(As[buf][m0 + 8][kk + 4 + c]);
            }
#pragma unroll
            for (int ni = 0; ni < 4; ni++) {
                int n0 = wn + ni * 8 + r;
                if (CVTB) {
                    bfr[ni][0] = f2tf(Bs[buf][kk + c][n0]);
                    bfr[ni][1] = f2tf(Bs[buf][kk + 4 + c][n0]);
                } else {
                    bfr[ni][0] = __float_as_uint(Bs[buf][kk + c][n0]);
                    bfr[ni][1] = __float_as_uint(Bs[buf][kk + 4 + c][n0]);
                }
            }
#pragma unroll
            for (int mi = 0; mi < 4; mi++)
#pragma unroll
                for (int ni = 0; ni < 4; ni++) mma8(acc[mi][ni], a[mi], bfr[ni]);
        }
        __syncthreads();
    }

    int c2 = (lane & 3) * 2;
#pragma unroll
    for (int mi = 0; mi < 4; mi++) {
        int row0 = bm + wm + mi * 16 + r;
        int row1 = row0 + 8;
#pragma unroll
        for (int ni = 0; ni < 4; ni++) {
            int col = bn + wn + ni * 8 + c2;
            float v00 = acc[mi][ni][0], v01 = acc[mi][ni][1];
            float v10 = acc[mi][ni][2], v11 = acc[mi][ni][3];
            if (EPI == 0) {
                int h = col / 192;
                int f = col - h * 192;
                int which = f >> 6;
                int d = f & 63;
                float* dst = (which == 0) ? oq : (which == 1) ? okk : ov;
                {
                    int b_ = row0 >> 11, s_ = row0 & 2047;
                    size_t base = (((size_t)(b_ * 16 + h) * S_SEQ + s_) * HD + d);
                    dst[base] = tfr(v00);
                    dst[base + 1] = tfr(v01);
                }
                {
                    int b_ = row1 >> 11, s_ = row1 & 2047;
                    size_t base = (((size_t)(b_ * 16 + h) * S_SEQ + s_) * HD + d);
                    dst[base] = tfr(v10);
                    dst[base + 1] = tfr(v11);
                }
            } else if (EPI == 1) {
                float2 bv = *(const float2*)&bias[col];
                float2 r0 = *(const float2*)&res[(size_t)row0 * N + col];
                float2 r1 = *(const float2*)&res[(size_t)row1 * N + col];
                float2 o0, o1;
                o0.x = v00 + bv.x + r0.x; o0.y = v01 + bv.y + r0.y;
                o1.x = v10 + bv.x + r1.x; o1.y = v11 + bv.y + r1.y;
                *(float2*)&out[(size_t)row0 * N + col] = o0;
                *(float2*)&out[(size_t)row1 * N + col] = o1;
            } else {
                float2 bv = *(const float2*)&bias[col];
                float2 o0, o1;
                o0.x = tfr(geluf(v00 + bv.x)); o0.y = tfr(geluf(v01 + bv.y));
                o1.x = tfr(geluf(v10 + bv.x)); o1.y = tfr(geluf(v11 + bv.y));
                *(float2*)&out[(size_t)row0 * N + col] = o0;
                *(float2*)&out[(size_t)row1 * N + col] = o1;
            }
        }
    }
}

// ---------------- Tensor-core flash attention ----------------
// Block: 128 threads (4 warps), 64 q-rows per block (warp -> 16 rows).
// K/V tiles 64x64, double-buffered cp.async. S and PV on tf32 mma.
#define KS_STR 68
#define VS_STR 72
#define PS_STR 68
#define ATT_SMEM_BYTES ((2 * 64 * KS_STR + 2 * 64 * VS_STR + 64 * PS_STR) * 4)

__global__ void __launch_bounds__(128) attn_tc(const float* __restrict__ Qg,
                                               const float* __restrict__ Kg,
                                               const float* __restrict__ Vg,
                                               float* __restrict__ Og) {
    extern __shared__ float sm[];
    float* Ks = sm;                      // [2][64][KS_STR]
    float* Vs = sm + 2 * 64 * KS_STR;    // [2][64][VS_STR]
    float* Ps = Vs + 2 * 64 * VS_STR;    // [64][PS_STR]

    int tid = threadIdx.x, lane = tid & 31, warp = tid >> 5;
    int r = lane >> 2, cq = lane & 3;
    int q0 = blockIdx.x * 64, bh = blockIdx.y;
    const float* qp = Qg + (size_t)bh * S_SEQ * HD;
    const float* kp = Kg + (size_t)bh * S_SEQ * HD;
    const float* vp = Vg + (size_t)bh * S_SEQ * HD;

    // stage Q tile into Ps, then load per-warp A fragments (scaled by 1/8: exact in tf32)
#pragma unroll
    for (int j = 0; j < 8; j++) {
        int f = tid + 128 * j;
        int row = f >> 4, c4 = (f & 15) * 4;
        *(float4*)&Ps[row * PS_STR + c4] =
            *(const float4*)&qp[(size_t)(q0 + row) * HD + c4];
    }
    __syncthreads();
    unsigned qa[8][4];
    int qrow = warp * 16 + r;
#pragma unroll
    for (int kf = 0; kf < 8; kf++) {
        qa[kf][0] = __float_as_uint(Ps[qrow * PS_STR + kf * 8 + cq] * 0.125f);
        qa[kf][1] = __float_as_uint(Ps[(qrow + 8) * PS_STR + kf * 8 + cq] * 0.125f);
        qa[kf][2] = __float_as_uint(Ps[qrow * PS_STR + kf * 8 + 4 + cq] * 0.125f);
        qa[kf][3] = __float_as_uint(Ps[(qrow + 8) * PS_STR + kf * 8 + 4 + cq] * 0.125f);
    }
    __syncthreads();

    float m0 = -1e30f, m1 = -1e30f, l0 = 0.f, l1 = 0.f;
    float oacc[8][4];
#pragma unroll
    for (int ni = 0; ni < 8; ni++)
#pragma unroll
        for (int q = 0; q < 4; q++) oacc[ni][q] = 0.f;

    // prologue load tile 0
    {
        const float* kg = kp;
        const float* vg = vp;
#pragma unroll
        for (int j = 0; j < 8; j++) {
            int f = tid + 128 * j;
            int row = f >> 4, c4 = (f & 15) * 4;
            cpasync16(&Ks[row * KS_STR + c4], &kg[(size_t)row * HD + c4]);
            cpasync16(&Vs[row * VS_STR + c4], &vg[(size_t)row * HD + c4]);
        }
        cpcommit();
    }

    const int NT = S_SEQ / 64;
    for (int kt = 0; kt < NT; kt++) {
        int buf = kt & 1;
        if (kt + 1 < NT) {
            int nb = 1 - buf;
            const float* kg = kp + (size_t)(kt + 1) * 64 * HD;
            const float* vg = vp + (size_t)(kt + 1) * 64 * HD;
            float* kd = Ks + nb * 64 * KS_STR;
            float* vd = Vs + nb * 64 * VS_STR;
#pragma unroll
            for (int j = 0; j < 8; j++) {
                int f = tid + 128 * j;
                int row = f >> 4, c4 = (f & 15) * 4;
                cpasync16(&kd[row * KS_STR + c4], &kg[(size_t)row * HD + c4]);
                cpasync16(&vd[row * VS_STR + c4], &vg[(size_t)row * HD + c4]);
            }
            cpcommit();
            cpwait1();
        } else {
            cpwait0();
        }
        __syncthreads();
        const float* kb = Ks + buf * 64 * KS_STR;
        const float* vb = Vs + buf * 64 * VS_STR;

        // ---- S = (Q/8) @ K^T ----
        float s[8][4];
#pragma unroll
        for (int ni = 0; ni < 8; ni++)
#pragma unroll
            for (int q = 0; q < 4; q++) s[ni][q] = 0.f;
#pragma unroll
        for (int kf = 0; kf < 8; kf++) {
#pragma unroll
            for (int ni = 0; ni < 8; ni++) {
                unsigned bb[2];
                bb[0] = __float_as_uint(kb[(r + 8 * ni) * KS_STR + kf * 8 + cq]);
                bb[1] = __float_as_uint(kb[(r + 8 * ni) * KS_STR + kf * 8 + 4 + cq]);
                mma8(s[ni], qa[kf], bb);
            }
        }

        // ---- online softmax on fragments (rows r and r+8) ----
        float rm0 = -1e30f, rm1 = -1e30f;
#pragma unroll
        for (int ni = 0; ni < 8; ni++) {
            rm0 = fmaxf(rm0, fmaxf(s[ni][0], s[ni][1]));
            rm1 = fmaxf(rm1, fmaxf(s[ni][2], s[ni][3]));
        }
        rm0 = fmaxf(rm0, __shfl_xor_sync(0xffffffffu, rm0, 1));
        rm0 = fmaxf(rm0, __shfl_xor_sync(0xffffffffu, rm0, 2));
        rm1 = fmaxf(rm1, __shfl_xor_sync(0xffffffffu, rm1, 1));
        rm1 = fmaxf(rm1, __shfl_xor_sync(0xffffffffu, rm1, 2));
        float mn0 = fmaxf(m0, rm0), mn1 = fmaxf(m1, rm1);
        float corr0 = __expf(m0 - mn0), corr1 = __expf(m1 - mn1);
        m0 = mn0; m1 = mn1;
        float rs0 = 0.f, rs1 = 0.f;
#pragma unroll
        for (int ni = 0; ni < 8; ni++) {
            float p0 = __expf(s[ni][0] - mn0);
            float p1 = __expf(s[ni][1] - mn0);
            float p2 = __expf(s[ni][2] - mn1);
            float p3 = __expf(s[ni][3] - mn1);
            rs0 += p0 + p1; rs1 += p2 + p3;
            float2 w0; w0.x = tfr(p0); w0.y = tfr(p1);
            float2 w1; w1.x = tfr(p2); w1.y = tfr(p3);
            *(float2*)&Ps[qrow * PS_STR + ni * 8 + 2 * cq] = w0;
            *(float2*)&Ps[(qrow + 8) * PS_STR + ni * 8 + 2 * cq] = w1;
        }
        rs0 += __shfl_xor_sync(0xffffffffu, rs0, 1);
        rs0 += __shfl_xor_sync(0xffffffffu, rs0, 2);
        rs1 += __shfl_xor_sync(0xffffffffu, rs1, 1);
        rs1 += __shfl_xor_sync(0xffffffffu, rs1, 2);
        l0 = l0 * corr0 + rs0;
        l1 = l1 * corr1 + rs1;
#pragma unroll
        for (int ni = 0; ni < 8; ni++) {
            oacc[ni][0] *= corr0; oacc[ni][1] *= corr0;
            oacc[ni][2] *= corr1; oacc[ni][3] *= corr1;
        }
        __syncwarp();  // P rows are private to this warp

        // ---- O += P @ V ----
#pragma unroll
        for (int kf = 0; kf < 8; kf++) {
            unsigned pa[4];
            pa[0] = __float_as_uint(Ps[qrow * PS_STR + kf * 8 + cq]);
            pa[1] = __float_as_uint(Ps[(qrow + 8) * PS_STR + kf * 8 + cq]);
            pa[2] = __float_as_uint(Ps[qrow * PS_STR + kf * 8 + 4 + cq]);
            pa[3] = __float_as_uint(Ps[(qrow + 8) * PS_STR + kf * 8 + 4 + cq]);
#pragma unroll
            for (int ni = 0; ni < 8; ni++) {
                unsigned bb[2];
                bb[0] = __float_as_uint(vb[(kf * 8 + cq) * VS_STR + r + 8 * ni]);
                bb[1] = __float_as_uint(vb[(kf * 8 + 4 + cq) * VS_STR + r + 8 * ni]);
                mma8(oacc[ni], pa, bb);
            }
        }
        __syncthreads();
    }

    // normalize + write to concat-head layout (rounded: feeds proj GEMM A)
    int b_ = bh >> 4, h = bh & 15;
    float inv0 = 1.0f / l0, inv1 = 1.0f / l1;
    size_t t0 = ((size_t)b_ * S_SEQ + q0 + qrow) * D_EMB + h * HD;
    size_t t1 = ((size_t)b_ * S_SEQ + q0 + qrow + 8) * D_EMB + h * HD;
#pragma unroll
    for (int ni = 0; ni < 8; ni++) {
        int d = ni * 8 + 2 * cq;
        float2 w0; w0.x = tfr(oacc[ni][0] * inv0); w0.y = tfr(oacc[ni][1] * inv0);
        float2 w1; w1.x = tfr(oacc[ni][2] * inv1); w1.y = tfr(oacc[ni][3] * inv1);
        *(float2*)&Og[t0 + d] = w0;
        *(float2*)&Og[t1 + d] = w1;
    }
}

// ---------------- launch ----------------
extern "C" void kernel_launch(void* const* d_in, const int* in_sizes, int n_in,
                              void* d_out, int out_size) {
    const float* x = (const float*)d_in[0];
    const float* w_qkv = (const float*)d_in[1];
    const float* w_hproj = (const float*)d_in[2];
    const float* b_hproj = (const float*)d_in[3];
    const float* w_out = (const float*)d_in[4];
    const float* b_out = (const float*)d_in[5];
    const float* w_fc1 = (const float*)d_in[6];
    const float* b_fc1 = (const float*)d_in[7];
    const float* w_fc2 = (const float*)d_in[8];
    const float* b_fc2 = (const float*)d_in[9];
    const float* g1 = (const float*)d_in[10];
    const float* be1 = (const float*)d_in[11];
    const float* g2 = (const float*)d_in[12];
    const float* be2 = (const float*)d_in[13];
    float* out = (float*)d_out;

    float *xn, *q, *k, *v, *o, *x1, *hb, *W2, *b2, *wqkvp;
    cudaGetSymbolAddress((void**)&xn, g_xn);
    cudaGetSymbolAddress((void**)&q, g_q);
    cudaGetSymbolAddress((void**)&k, g_k);
    cudaGetSymbolAddress((void**)&v, g_v);
    cudaGetSymbolAddress((void**)&o, g_o);
    cudaGetSymbolAddress((void**)&x1, g_x1);
    cudaGetSymbolAddress((void**)&hb, g_h);
    cudaGetSymbolAddress((void**)&W2, g_W2);
    cudaGetSymbolAddress((void**)&b2, g_b2);
    cudaGetSymbolAddress((void**)&wqkvp, g_wqkvp);

    cudaFuncSetAttribute(attn_tc, cudaFuncAttributeMaxDynamicSharedMemorySize,
                         ATT_SMEM_BYTES);

    // LN1 + weight prep
    ln_kernel<<<T_TOK, 256>>>(x, g1, be1, xn);
    repack_qkv_kernel<<<3072, 256>>>(w_qkv, wqkvp);
    fuse_w2_kernel<<<dim3(16, 16), 256>>>(w_hproj, w_out, W2);
    bias2_kernel<<<16, 256>>>(b_hproj, b_out, w_out, b2);
    // QKV: [4096,1024] x [1024,3072], scatter to per-head q/k/v (tf32-rounded)
    gemm_tc<0, false><<<dim3(32, 24), 256>>>(xn, wqkvp, T_TOK, 3072, D_EMB,
                                             nullptr, nullptr, nullptr, q, k, v);
    // tensor-core flash attention -> concat-head layout (rounded)
    attn_tc<<<dim3(S_SEQ / 64, 32), 128, ATT_SMEM_BYTES>>>(q, k, v, o);
    // out projection (fused hproj+wout) + bias2 + residual -> x1
    gemm_tc<1, false><<<dim3(32, 8), 256>>>(o, W2, T_TOK, D_EMB, D_EMB,
                                            b2, x, x1, nullptr, nullptr, nullptr);
    // LN2
    ln_kernel<<<T_TOK, 256>>>(x1, g2, be2, xn);
    // FC1 + bias + exact GELU (rounded)
    gemm_tc<2, true><<<dim3(32, 32), 256>>>(xn, w_fc1, T_TOK, MLP_DIM, D_EMB,
                                            b_fc1, nullptr, hb, nullptr, nullptr, nullptr);
    // FC2 + bias + residual x1 -> out (full fp32 epilogue)
    gemm_tc<1, true><<<dim3(32, 8), 256>>>(hb, w_fc2, T_TOK, D_EMB, MLP_DIM,
                                           b_fc2, x1, out, nullptr, nullptr, nullptr);
}

// round 5
// speedup vs baseline: 3.2989x; 1.0066x over previous
#include <cuda_runtime.h>
#include <math.h>

#define T_TOK 4096
#define D_EMB 1024
#define S_SEQ 2048
#define NH 16
#define HD 64
#define MLP_DIM 4096

// -------- scratch (device globals; no allocation allowed) --------
__device__ float g_xn[T_TOK * D_EMB];
__device__ float g_q[32 * S_SEQ * HD];
__device__ float g_k[32 * S_SEQ * HD];
__device__ float g_v[32 * S_SEQ * HD];
__device__ float g_o[T_TOK * D_EMB];
__device__ float g_x1[T_TOK * D_EMB];
__device__ float g_h[T_TOK * MLP_DIM];
__device__ float g_W2[D_EMB * D_EMB];
__device__ float g_b2[D_EMB];
__device__ float g_wqkvp[D_EMB * 3 * HD * NH];  // [1024][3072] packed

// ---------------- helpers ----------------
__device__ __forceinline__ unsigned f2tf(float x) {
    unsigned u;
    asm("cvt.rna.tf32.f32 %0, %1;" : "=r"(u) : "f"(x));
    return u;
}
__device__ __forceinline__ float tfr(float x) { return __uint_as_float(f2tf(x)); }
__device__ __forceinline__ float geluf(float x) {
    return 0.5f * x * (1.0f + erff(x * 0.70710678118654752f));
}
__device__ __forceinline__ void cpasync16(float* s, const float* g) {
    unsigned sa = (unsigned)__cvta_generic_to_shared(s);
    asm volatile("cp.async.cg.shared.global [%0], [%1], 16;" :: "r"(sa), "l"(g));
}
__device__ __forceinline__ void cpcommit() { asm volatile("cp.async.commit_group;"); }
__device__ __forceinline__ void cpwait0() { asm volatile("cp.async.wait_group 0;"); }
__device__ __forceinline__ void cpwait1() { asm volatile("cp.async.wait_group 1;"); }
__device__ __forceinline__ void mma8(float* d, const unsigned* a, const unsigned* b) {
    asm volatile(
        "mma.sync.aligned.m16n8k8.row.col.f32.tf32.tf32.f32 "
        "{%0,%1,%2,%3},{%4,%5,%6,%7},{%8,%9},{%0,%1,%2,%3};"
        : "+f"(d[0]), "+f"(d[1]), "+f"(d[2]), "+f"(d[3])
        : "r"(a[0]), "r"(a[1]), "r"(a[2]), "r"(a[3]), "r"(b[0]), "r"(b[1]));
}

// ---------------- LayerNorm (rounds output to tf32 for GEMM A use) ----------------
__global__ void __launch_bounds__(256) ln_kernel(const float* __restrict__ in,
                                                 const float* __restrict__ g,
                                                 const float* __restrict__ b,
                                                 float* __restrict__ out) {
    __shared__ float s_sum[256], s_sq[256];
    int row = blockIdx.x, tid = threadIdx.x;
    float4 v = ((const float4*)(in + (size_t)row * D_EMB))[tid];
    s_sum[tid] = v.x + v.y + v.z + v.w;
    s_sq[tid] = v.x * v.x + v.y * v.y + v.z * v.z + v.w * v.w;
    __syncthreads();
    for (int s = 128; s > 0; s >>= 1) {
        if (tid < s) { s_sum[tid] += s_sum[tid + s]; s_sq[tid] += s_sq[tid + s]; }
        __syncthreads();
    }
    float mean = s_sum[0] * (1.0f / D_EMB);
    float var = s_sq[0] * (1.0f / D_EMB) - mean * mean;
    float inv = rsqrtf(var + 1e-5f);
    float4 gg = ((const float4*)g)[tid];
    float4 bb = ((const float4*)b)[tid];
    float4 r;
    r.x = tfr((v.x - mean) * inv * gg.x + bb.x);
    r.y = tfr((v.y - mean) * inv * gg.y + bb.y);
    r.z = tfr((v.z - mean) * inv * gg.z + bb.z);
    r.w = tfr((v.w - mean) * inv * gg.w + bb.w);
    ((float4*)(out + (size_t)row * D_EMB))[tid] = r;
}

// ---------------- pack w_qkv [H][D][192] -> [D][H*192], tf32-rounded ----------------
__global__ void __launch_bounds__(256) repack_qkv_kernel(const float* __restrict__ w,
                                                         float* __restrict__ wp) {
    int i = blockIdx.x * 256 + threadIdx.x;
    int n4 = i % 768, d = i / 768;
    int n = n4 * 4;
    int h = n / 192, f = n - h * 192;
    float4 v = *(const float4*)&w[((size_t)h * D_EMB + d) * 192 + f];
    v.x = tfr(v.x); v.y = tfr(v.y); v.z = tfr(v.z); v.w = tfr(v.w);
    *(float4*)&wp[(size_t)d * 3072 + n] = v;
}

// ---------------- Fuse W2 = blockdiag(w_hproj) @ w_out (tf32-rounded) ----------------
__global__ void __launch_bounds__(256) fuse_w2_kernel(const float* __restrict__ whp,
                                                      const float* __restrict__ wout,
                                                      float* __restrict__ W2) {
    __shared__ float hp[64 * 64];
    __shared__ float wo[64 * 64];
    int h = blockIdx.x, nt = blockIdx.y, tid = threadIdx.x;
#pragma unroll
    for (int j = 0; j < 4; j++) {
        int f = tid + 256 * j;
        ((float4*)hp)[f] = ((const float4*)(whp + (size_t)h * 4096))[f];
        int r = f >> 4, c4 = f & 15;
        *(float4*)&wo[r * 64 + c4 * 4] =
            *(const float4*)&wout[(size_t)(h * 64 + r) * D_EMB + nt * 64 + c4 * 4];
    }
    __syncthreads();
    int ty = tid >> 4, tx = tid & 15;
#pragma unroll
    for (int i = 0; i < 4; i++) {
        int d = ty * 4 + i;
#pragma unroll
        for (int j = 0; j < 4; j++) {
            int e = tx * 4 + j;
            float acc = 0.f;
#pragma unroll 8
            for (int k = 0; k < 64; k++) acc += hp[d * 64 + k] * wo[k * 64 + e];
            W2[(size_t)(h * 64 + d) * D_EMB + nt * 64 + e] = tfr(acc);
        }
    }
}

// bias2[e] = b_out[e] + sum_i b_hproj_flat[i] * w_out[i][e]
// 64 blocks; each block: 16 e-columns x 16 i-chunks of 64
__global__ void __launch_bounds__(256) bias2_kernel(const float* __restrict__ bhp,
                                                    const float* __restrict__ bout,
                                                    const float* __restrict__ wout,
                                                    float* __restrict__ b2) {
    __shared__ float part[16][16];
    int tid = threadIdx.x;
    int ec = tid & 15;
    int e = blockIdx.x * 16 + ec;
    int chunk = tid >> 4;
    float acc = 0.f;
    int i0 = chunk * 64;
#pragma unroll 8
    for (int i = i0; i < i0 + 64; i++) acc += bhp[i] * wout[(size_t)i * D_EMB + e];
    part[chunk][ec] = acc;
    __syncthreads();
    if (chunk == 0) {
        float s = bout[e];
#pragma unroll
        for (int cch = 0; cch < 16; cch++) s += part[cch][ec];
        b2[e] = s;
    }
}

// ---------------- tf32 tensor-core GEMM 128x128x16, 3-stage pipeline ----------------
#define BM 128
#define BN 128
#define BK 16
#define NSTG 3
#define A_STR 20
#define B_STR 136
#define GEMM_SMEM ((NSTG * (BM * A_STR + BK * B_STR)) * 4)

// EPI 0: qkv scatter (rounded), EPI 1: +bias +res (full fp32), EPI 2: gelu+bias (rounded)
// A operands are always pre-rounded to tf32; B frags cvt only when CVTB.
template <int EPI, bool CVTB>
__global__ void __launch_bounds__(256, 2) gemm_tc(
    const float* __restrict__ A, const float* __restrict__ B,
    int M, int N, int K,
    const float* __restrict__ bias, const float* __restrict__ res,
    float* __restrict__ out,
    float* __restrict__ oq, float* __restrict__ okk, float* __restrict__ ov) {
    extern __shared__ float smem_dyn[];
    float (*As)[BM][A_STR] = (float (*)[BM][A_STR])smem_dyn;
    float (*Bs)[BK][B_STR] = (float (*)[BK][B_STR])(smem_dyn + NSTG * BM * A_STR);

    int tid = threadIdx.x;
    int lane = tid & 31, warp = tid >> 5;
    int wm = (warp >> 2) * 64, wn = (warp & 3) * 32;
    int bm = blockIdx.x * BM, bn = blockIdx.y * BN;

    float acc[4][4][4];
#pragma unroll
    for (int mi = 0; mi < 4; mi++)
#pragma unroll
        for (int ni = 0; ni < 4; ni++)
#pragma unroll
            for (int q = 0; q < 4; q++) acc[mi][ni][q] = 0.f;

    const float* Ag = A + (size_t)bm * K;
    const float* Bg = B + bn;
    int a_row0 = tid >> 2, a_kc = (tid & 3) << 2;
    int b_row0 = tid >> 5, b_nc = (tid & 31) << 2;

    int T = K / BK;
    // prologue: issue stages for tiles 0 and 1 (T >= 2 at every call site)
#pragma unroll
    for (int p = 0; p < NSTG - 1; p++) {
        int k0 = p * BK;
        cpasync16(&As[p][a_row0][a_kc], Ag + (size_t)a_row0 * K + k0 + a_kc);
        cpasync16(&As[p][a_row0 + 64][a_kc], Ag + (size_t)(a_row0 + 64) * K + k0 + a_kc);
        cpasync16(&Bs[p][b_row0][b_nc], Bg + (size_t)(k0 + b_row0) * N + b_nc);
        cpasync16(&Bs[p][b_row0 + 8][b_nc], Bg + (size_t)(k0 + b_row0 + 8) * N + b_nc);
        cpcommit();
    }

    int r = lane >> 2, c = lane & 3;
    int buf = 0, nstage = NSTG - 1;
    for (int t = 0; t < T; t++) {
        // tile t ready: newest committed tile is t+1 (if it exists)
        if (t < T - 1) cpwait1(); else cpwait0();
        __syncthreads();
        // prefetch tile t+2 into the stage read at t-1 (barrier above protects it)
        if (t + 2 < T) {
            int k0 = (t + 2) * BK;
            int s = nstage;
            cpasync16(&As[s][a_row0][a_kc], Ag + (size_t)a_row0 * K + k0 + a_kc);
            cpasync16(&As[s][a_row0 + 64][a_kc], Ag + (size_t)(a_row0 + 64) * K + k0 + a_kc);
            cpasync16(&Bs[s][b_row0][b_nc], Bg + (size_t)(k0 + b_row0) * N + b_nc);
            cpasync16(&Bs[s][b_row0 + 8][b_nc], Bg + (size_t)(k0 + b_row0 + 8) * N + b_nc);
            cpcommit();
        }
        nstage = buf;  // stage just about to be consumed becomes the future write target

#pragma unroll
        for (int ks = 0; ks < 2; ks++) {
            int kk = ks * 8;
            unsigned a[4][4], bfr[4][2];
#pragma unroll
            for (int mi = 0; mi < 4; mi++) {
                int m0 = wm + mi * 16 + r;
                a[mi][0] = __float_as_uint(As[buf][m0][kk + c]);
                a[mi][1] = __float_as_uint(As[buf][m0 + 8][kk + c]);
                a[mi][2] = __float_as_uint(As[buf][m0][kk + 4 + c]);
                a[mi][3] = __float_as_uint(As[buf][m0 + 8][kk + 4 + c]);
            }
#pragma unroll
            for (int ni = 0; ni < 4; ni++) {
                int n0 = wn + ni * 8 + r;
                if (CVTB) {
                    bfr[ni][0] = f2tf(Bs[buf][kk + c][n0]);
                    bfr[ni][1] = f2tf(Bs[buf][kk + 4 + c][n0]);
                } else {
                    bfr[ni][0] = __float_as_uint(Bs[buf][kk + c][n0]);
                    bfr[ni][1] = __float_as_uint(Bs[buf][kk + 4 + c][n0]);
                }
            }
#pragma unroll
            for (int mi = 0; mi < 4; mi++)
#pragma unroll
                for (int ni = 0; ni < 4; ni++) mma8(acc[mi][ni], a[mi], bfr[ni]);
        }
        buf = (buf + 1 == NSTG) ? 0 : buf + 1;
    }

    int c2 = (lane & 3) * 2;
#pragma unroll
    for (int mi = 0; mi < 4; mi++) {
        int row0 = bm + wm + mi * 16 + r;
        int row1 = row0 + 8;
#pragma unroll
        for (int ni = 0; ni < 4; ni++) {
            int col = bn + wn + ni * 8 + c2;
            float v00 = acc[mi][ni][0], v01 = acc[mi][ni][1];
            float v10 = acc[mi][ni][2], v11 = acc[mi][ni][3];
            if (EPI == 0) {
                int h = col / 192;
                int f = col - h * 192;
                int which = f >> 6;
                int d = f & 63;
                float* dst = (which == 0) ? oq : (which == 1) ? okk : ov;
                {
                    int b_ = row0 >> 11, s_ = row0 & 2047;
                    size_t base = (((size_t)(b_ * 16 + h) * S_SEQ + s_) * HD + d);
                    dst[base] = tfr(v00);
                    dst[base + 1] = tfr(v01);
                }
                {
                    int b_ = row1 >> 11, s_ = row1 & 2047;
                    size_t base = (((size_t)(b_ * 16 + h) * S_SEQ + s_) * HD + d);
                    dst[base] = tfr(v10);
                    dst[base + 1] = tfr(v11);
                }
            } else if (EPI == 1) {
                float2 bv = *(const float2*)&bias[col];
                float2 r0 = *(const float2*)&res[(size_t)row0 * N + col];
                float2 r1 = *(const float2*)&res[(size_t)row1 * N + col];
                float2 o0, o1;
                o0.x = v00 + bv.x + r0.x; o0.y = v01 + bv.y + r0.y;
                o1.x = v10 + bv.x + r1.x; o1.y = v11 + bv.y + r1.y;
                *(float2*)&out[(size_t)row0 * N + col] = o0;
                *(float2*)&out[(size_t)row1 * N + col] = o1;
            } else {
                float2 bv = *(const float2*)&bias[col];
                float2 o0, o1;
                o0.x = tfr(geluf(v00 + bv.x)); o0.y = tfr(geluf(v01 + bv.y));
                o1.x = tfr(geluf(v10 + bv.x)); o1.y = tfr(geluf(v11 + bv.y));
                *(float2*)&out[(size_t)row0 * N + col] = o0;
                *(float2*)&out[(size_t)row1 * N + col] = o1;
            }
        }
    }
}

// ---------------- Tensor-core flash attention ----------------
// Block: 128 threads (4 warps), 64 q-rows per block (warp -> 16 rows).
// K/V tiles 64x64, double-buffered cp.async. S and PV on tf32 mma.
#define KS_STR 68
#define VS_STR 72
#define PS_STR 68
#define ATT_SMEM_BYTES ((2 * 64 * KS_STR + 2 * 64 * VS_STR + 64 * PS_STR) * 4)

__global__ void __launch_bounds__(128) attn_tc(const float* __restrict__ Qg,
                                               const float* __restrict__ Kg,
                                               const float* __restrict__ Vg,
                                               float* __restrict__ Og) {
    extern __shared__ float sm[];
    float* Ks = sm;                      // [2][64][KS_STR]
    float* Vs = sm + 2 * 64 * KS_STR;    // [2][64][VS_STR]
    float* Ps = Vs + 2 * 64 * VS_STR;    // [64][PS_STR]

    int tid = threadIdx.x, lane = tid & 31, warp = tid >> 5;
    int r = lane >> 2, cq = lane & 3;
    int q0 = blockIdx.x * 64, bh = blockIdx.y;
    const float* qp = Qg + (size_t)bh * S_SEQ * HD;
    const float* kp = Kg + (size_t)bh * S_SEQ * HD;
    const float* vp = Vg + (size_t)bh * S_SEQ * HD;

    // stage Q tile into Ps, then load per-warp A fragments (scaled by 1/8: exact in tf32)
#pragma unroll
    for (int j = 0; j < 8; j++) {
        int f = tid + 128 * j;
        int row = f >> 4, c4 = (f & 15) * 4;
        *(float4*)&Ps[row * PS_STR + c4] =
            *(const float4*)&qp[(size_t)(q0 + row) * HD + c4];
    }
    __syncthreads();
    unsigned qa[8][4];
    int qrow = warp * 16 + r;
#pragma unroll
    for (int kf = 0; kf < 8; kf++) {
        qa[kf][0] = __float_as_uint(Ps[qrow * PS_STR + kf * 8 + cq] * 0.125f);
        qa[kf][1] = __float_as_uint(Ps[(qrow + 8) * PS_STR + kf * 8 + cq] * 0.125f);
        qa[kf][2] = __float_as_uint(Ps[qrow * PS_STR + kf * 8 + 4 + cq] * 0.125f);
        qa[kf][3] = __float_as_uint(Ps[(qrow + 8) * PS_STR + kf * 8 + 4 + cq] * 0.125f);
    }
    __syncthreads();

    float m0 = -1e30f, m1 = -1e30f, l0 = 0.f, l1 = 0.f;
    float oacc[8][4];
#pragma unroll
    for (int ni = 0; ni < 8; ni++)
#pragma unroll
        for (int q = 0; q < 4; q++) oacc[ni][q] = 0.f;

    // prologue load tile 0
    {
        const float* kg = kp;
        const float* vg = vp;
#pragma unroll
        for (int j = 0; j < 8; j++) {
            int f = tid + 128 * j;
            int row = f >> 4, c4 = (f & 15) * 4;
            cpasync16(&Ks[row * KS_STR + c4], &kg[(size_t)row * HD + c4]);
            cpasync16(&Vs[row * VS_STR + c4], &vg[(size_t)row * HD + c4]);
        }
        cpcommit();
    }

    const int NT = S_SEQ / 64;
    for (int kt = 0; kt < NT; kt++) {
        int buf = kt & 1;
        if (kt + 1 < NT) {
            int nb = 1 - buf;
            const float* kg = kp + (size_t)(kt + 1) * 64 * HD;
            const float* vg = vp + (size_t)(kt + 1) * 64 * HD;
            float* kd = Ks + nb * 64 * KS_STR;
            float* vd = Vs + nb * 64 * VS_STR;
#pragma unroll
            for (int j = 0; j < 8; j++) {
                int f = tid + 128 * j;
                int row = f >> 4, c4 = (f & 15) * 4;
                cpasync16(&kd[row * KS_STR + c4], &kg[(size_t)row * HD + c4]);
                cpasync16(&vd[row * VS_STR + c4], &vg[(size_t)row * HD + c4]);
            }
            cpcommit();
            cpwait1();
        } else {
            cpwait0();
        }
        __syncthreads();
        const float* kb = Ks + buf * 64 * KS_STR;
        const float* vb = Vs + buf * 64 * VS_STR;

        // ---- S = (Q/8) @ K^T ----
        float s[8][4];
#pragma unroll
        for (int ni = 0; ni < 8; ni++)
#pragma unroll
            for (int q = 0; q < 4; q++) s[ni][q] = 0.f;
#pragma unroll
        for (int kf = 0; kf < 8; kf++) {
#pragma unroll
            for (int ni = 0; ni < 8; ni++) {
                unsigned bb[2];
                bb[0] = __float_as_uint(kb[(r + 8 * ni) * KS_STR + kf * 8 + cq]);
                bb[1] = __float_as_uint(kb[(r + 8 * ni) * KS_STR + kf * 8 + 4 + cq]);
                mma8(s[ni], qa[kf], bb);
            }
        }

        // ---- online softmax on fragments (rows r and r+8) ----
        float rm0 = -1e30f, rm1 = -1e30f;
#pragma unroll
        for (int ni = 0; ni < 8; ni++) {
            rm0 = fmaxf(rm0, fmaxf(s[ni][0], s[ni][1]));
            rm1 = fmaxf(rm1, fmaxf(s[ni][2], s[ni][3]));
        }
        rm0 = fmaxf(rm0, __shfl_xor_sync(0xffffffffu, rm0, 1));
        rm0 = fmaxf(rm0, __shfl_xor_sync(0xffffffffu, rm0, 2));
        rm1 = fmaxf(rm1, __shfl_xor_sync(0xffffffffu, rm1, 1));
        rm1 = fmaxf(rm1, __shfl_xor_sync(0xffffffffu, rm1, 2));
        float mn0 = fmaxf(m0, rm0), mn1 = fmaxf(m1, rm1);
        float corr0 = __expf(m0 - mn0), corr1 = __expf(m1 - mn1);
        m0 = mn0; m1 = mn1;
        float rs0 = 0.f, rs1 = 0.f;
#pragma unroll
        for (int ni = 0; ni < 8; ni++) {
            float p0 = __expf(s[ni][0] - mn0);
            float p1 = __expf(s[ni][1] - mn0);
            float p2 = __expf(s[ni][2] - mn1);
            float p3 = __expf(s[ni][3] - mn1);
            rs0 += p0 + p1; rs1 += p2 + p3;
            float2 w0; w0.x = tfr(p0); w0.y = tfr(p1);
            float2 w1; w1.x = tfr(p2); w1.y = tfr(p3);
            *(float2*)&Ps[qrow * PS_STR + ni * 8 + 2 * cq] = w0;
            *(float2*)&Ps[(qrow + 8) * PS_STR + ni * 8 + 2 * cq] = w1;
        }
        rs0 += __shfl_xor_sync(0xffffffffu, rs0, 1);
        rs0 += __shfl_xor_sync(0xffffffffu, rs0, 2);
        rs1 += __shfl_xor_sync(0xffffffffu, rs1, 1);
        rs1 += __shfl_xor_sync(0xffffffffu, rs1, 2);
        l0 = l0 * corr0 + rs0;
        l1 = l1 * corr1 + rs1;
#pragma unroll
        for (int ni = 0; ni < 8; ni++) {
            oacc[ni][0] *= corr0; oacc[ni][1] *= corr0;
            oacc[ni][2] *= corr1; oacc[ni][3] *= corr1;
        }
        __syncwarp();  // P rows are private to this warp

        // ---- O += P @ V ----
#pragma unroll
        for (int kf = 0; kf < 8; kf++) {
            unsigned pa[4];
            pa[0] = __float_as_uint(Ps[qrow * PS_STR + kf * 8 + cq]);
            pa[1] = __float_as_uint(Ps[(qrow + 8) * PS_STR + kf * 8 + cq]);
            pa[2] = __float_as_uint(Ps[qrow * PS_STR + kf * 8 + 4 + cq]);
            pa[3] = __float_as_uint(Ps[(qrow + 8) * PS_STR + kf * 8 + 4 + cq]);
#pragma unroll
            for (int ni = 0; ni < 8; ni++) {
                unsigned bb[2];
                bb[0] = __float_as_uint(vb[(kf * 8 + cq) * VS_STR + r + 8 * ni]);
                bb[1] = __float_as_uint(vb[(kf * 8 + 4 + cq) * VS_STR + r + 8 * ni]);
                mma8(oacc[ni], pa, bb);
            }
        }
        __syncthreads();
    }

    // normalize + write to concat-head layout (rounded: feeds proj GEMM A)
    int b_ = bh >> 4, h = bh & 15;
    float inv0 = 1.0f / l0, inv1 = 1.0f / l1;
    size_t t0 = ((size_t)b_ * S_SEQ + q0 + qrow) * D_EMB + h * HD;
    size_t t1 = ((size_t)b_ * S_SEQ + q0 + qrow + 8) * D_EMB + h * HD;
#pragma unroll
    for (int ni = 0; ni < 8; ni++) {
        int d = ni * 8 + 2 * cq;
        float2 w0; w0.x = tfr(oacc[ni][0] * inv0); w0.y = tfr(oacc[ni][1] * inv0);
        float2 w1; w1.x = tfr(oacc[ni][2] * inv1); w1.y = tfr(oacc[ni][3] * inv1);
        *(float2*)&Og[t0 + d] = w0;
        *(float2*)&Og[t1 + d] = w1;
    }
}

// ---------------- launch ----------------
extern "C" void kernel_launch(void* const* d_in, const int* in_sizes, int n_in,
                              void* d_out, int out_size) {
    const float* x = (const float*)d_in[0];
    const float* w_qkv = (const float*)d_in[1];
    const float* w_hproj = (const float*)d_in[2];
    const float* b_hproj = (const float*)d_in[3];
    const float* w_out = (const float*)d_in[4];
    const float* b_out = (const float*)d_in[5];
    const float* w_fc1 = (const float*)d_in[6];
    const float* b_fc1 = (const float*)d_in[7];
    const float* w_fc2 = (const float*)d_in[8];
    const float* b_fc2 = (const float*)d_in[9];
    const float* g1 = (const float*)d_in[10];
    const float* be1 = (const float*)d_in[11];
    const float* g2 = (const float*)d_in[12];
    const float* be2 = (const float*)d_in[13];
    float* out = (float*)d_out;

    float *xn, *q, *k, *v, *o, *x1, *hb, *W2, *b2, *wqkvp;
    cudaGetSymbolAddress((void**)&xn, g_xn);
    cudaGetSymbolAddress((void**)&q, g_q);
    cudaGetSymbolAddress((void**)&k, g_k);
    cudaGetSymbolAddress((void**)&v, g_v);
    cudaGetSymbolAddress((void**)&o, g_o);
    cudaGetSymbolAddress((void**)&x1, g_x1);
    cudaGetSymbolAddress((void**)&hb, g_h);
    cudaGetSymbolAddress((void**)&W2, g_W2);
    cudaGetSymbolAddress((void**)&b2, g_b2);
    cudaGetSymbolAddress((void**)&wqkvp, g_wqkvp);

    cudaFuncSetAttribute(attn_tc, cudaFuncAttributeMaxDynamicSharedMemorySize,
                         ATT_SMEM_BYTES);
    cudaFuncSetAttribute(gemm_tc<0, false>, cudaFuncAttributeMaxDynamicSharedMemorySize,
                         GEMM_SMEM);
    cudaFuncSetAttribute(gemm_tc<1, false>, cudaFuncAttributeMaxDynamicSharedMemorySize,
                         GEMM_SMEM);
    cudaFuncSetAttribute(gemm_tc<2, true>, cudaFuncAttributeMaxDynamicSharedMemorySize,
                         GEMM_SMEM);
    cudaFuncSetAttribute(gemm_tc<1, true>, cudaFuncAttributeMaxDynamicSharedMemorySize,
                         GEMM_SMEM);

    // LN1 + weight prep
    ln_kernel<<<T_TOK, 256>>>(x, g1, be1, xn);
    repack_qkv_kernel<<<3072, 256>>>(w_qkv, wqkvp);
    fuse_w2_kernel<<<dim3(16, 16), 256>>>(w_hproj, w_out, W2);
    bias2_kernel<<<64, 256>>>(b_hproj, b_out, w_out, b2);
    // QKV: [4096,1024] x [1024,3072], scatter to per-head q/k/v (tf32-rounded)
    gemm_tc<0, false><<<dim3(32, 24), 256, GEMM_SMEM>>>(xn, wqkvp, T_TOK, 3072, D_EMB,
                                                        nullptr, nullptr, nullptr, q, k, v);
    // tensor-core flash attention -> concat-head layout (rounded)
    attn_tc<<<dim3(S_SEQ / 64, 32), 128, ATT_SMEM_BYTES>>>(q, k, v, o);
    // out projection (fused hproj+wout) + bias2 + residual -> x1
    gemm_tc<1, false><<<dim3(32, 8), 256, GEMM_SMEM>>>(o, W2, T_TOK, D_EMB, D_EMB,
                                                       b2, x, x1, nullptr, nullptr, nullptr);
    // LN2
    ln_kernel<<<T_TOK, 256>>>(x1, g2, be2, xn);
    // FC1 + bias + exact GELU (rounded)
    gemm_tc<2, true><<<dim3(32, 32), 256, GEMM_SMEM>>>(xn, w_fc1, T_TOK, MLP_DIM, D_EMB,
                                                       b_fc1, nullptr, hb, nullptr, nullptr, nullptr);
    // FC2 + bias + residual x1 -> out (full fp32 epilogue)
    gemm_tc<1, true><<<dim3(32, 8), 256, GEMM_SMEM>>>(hb, w_fc2, T_TOK, D_EMB, MLP_DIM,
                                                      b_fc2, x1, out, nullptr, nullptr, nullptr);
}

// round 6
// speedup vs baseline: 4.9317x; 1.4950x over previous
#include <cuda_runtime.h>
#include <cuda_fp16.h>
#include <math.h>

#define T_TOK 4096
#define D_EMB 1024
#define S_SEQ 2048
#define NH 16
#define HD 64
#define MLP_DIM 4096

// -------- scratch (device globals; no allocation allowed) --------
__device__ __half g_xnh[T_TOK * D_EMB];
__device__ float g_q[32 * S_SEQ * HD];
__device__ float g_k[32 * S_SEQ * HD];
__device__ float g_v[32 * S_SEQ * HD];
__device__ __half g_oh[T_TOK * D_EMB];
__device__ float g_x1[T_TOK * D_EMB];
__device__ __half g_hh[T_TOK * MLP_DIM];
__device__ __half g_W2h[D_EMB * D_EMB];
__device__ float g_b2[D_EMB];
__device__ __half g_wqkvph[D_EMB * 3 * HD * NH];   // [1024][3072]
__device__ __half g_wf1h[D_EMB * MLP_DIM];
__device__ __half g_wf2h[MLP_DIM * D_EMB];

// ---------------- helpers ----------------
__device__ __forceinline__ unsigned f2tf(float x) {
    unsigned u;
    asm("cvt.rna.tf32.f32 %0, %1;" : "=r"(u) : "f"(x));
    return u;
}
__device__ __forceinline__ float tfr(float x) { return __uint_as_float(f2tf(x)); }
__device__ __forceinline__ float geluf(float x) {
    return 0.5f * x * (1.0f + erff(x * 0.70710678118654752f));
}
__device__ __forceinline__ void cpasync16(void* s, const void* g) {
    unsigned sa = (unsigned)__cvta_generic_to_shared(s);
    asm volatile("cp.async.cg.shared.global [%0], [%1], 16;" :: "r"(sa), "l"(g));
}
__device__ __forceinline__ void cpcommit() { asm volatile("cp.async.commit_group;"); }
__device__ __forceinline__ void cpwait0() { asm volatile("cp.async.wait_group 0;"); }
__device__ __forceinline__ void cpwait1() { asm volatile("cp.async.wait_group 1;"); }
__device__ __forceinline__ void mma8(float* d, const unsigned* a, const unsigned* b) {
    asm volatile(
        "mma.sync.aligned.m16n8k8.row.col.f32.tf32.tf32.f32 "
        "{%0,%1,%2,%3},{%4,%5,%6,%7},{%8,%9},{%0,%1,%2,%3};"
        : "+f"(d[0]), "+f"(d[1]), "+f"(d[2]), "+f"(d[3])
        : "r"(a[0]), "r"(a[1]), "r"(a[2]), "r"(a[3]), "r"(b[0]), "r"(b[1]));
}
__device__ __forceinline__ void mma16h(float* d, const unsigned* a, const unsigned* b) {
    asm volatile(
        "mma.sync.aligned.m16n8k16.row.col.f32.f16.f16.f32 "
        "{%0,%1,%2,%3},{%4,%5,%6,%7},{%8,%9},{%0,%1,%2,%3};"
        : "+f"(d[0]), "+f"(d[1]), "+f"(d[2]), "+f"(d[3])
        : "r"(a[0]), "r"(a[1]), "r"(a[2]), "r"(a[3]), "r"(b[0]), "r"(b[1]));
}
__device__ __forceinline__ void ldsm4(unsigned* r, unsigned addr) {
    asm volatile("ldmatrix.sync.aligned.m8n8.x4.shared.b16 {%0,%1,%2,%3}, [%4];"
        : "=r"(r[0]), "=r"(r[1]), "=r"(r[2]), "=r"(r[3]) : "r"(addr));
}
__device__ __forceinline__ void ldsm4t(unsigned* r, unsigned addr) {
    asm volatile("ldmatrix.sync.aligned.m8n8.x4.trans.shared.b16 {%0,%1,%2,%3}, [%4];"
        : "=r"(r[0]), "=r"(r[1]), "=r"(r[2]), "=r"(r[3]) : "r"(addr));
}

// ---------------- LayerNorm -> half ----------------
__global__ void __launch_bounds__(256) ln_kernel(const float* __restrict__ in,
                                                 const float* __restrict__ g,
                                                 const float* __restrict__ b,
                                                 __half* __restrict__ out) {
    __shared__ float s_sum[256], s_sq[256];
    int row = blockIdx.x, tid = threadIdx.x;
    float4 v = ((const float4*)(in + (size_t)row * D_EMB))[tid];
    s_sum[tid] = v.x + v.y + v.z + v.w;
    s_sq[tid] = v.x * v.x + v.y * v.y + v.z * v.z + v.w * v.w;
    __syncthreads();
    for (int s = 128; s > 0; s >>= 1) {
        if (tid < s) { s_sum[tid] += s_sum[tid + s]; s_sq[tid] += s_sq[tid + s]; }
        __syncthreads();
    }
    float mean = s_sum[0] * (1.0f / D_EMB);
    float var = s_sq[0] * (1.0f / D_EMB) - mean * mean;
    float inv = rsqrtf(var + 1e-5f);
    float4 gg = ((const float4*)g)[tid];
    float4 bb = ((const float4*)b)[tid];
    __half2 h0 = __floats2half2_rn((v.x - mean) * inv * gg.x + bb.x,
                                   (v.y - mean) * inv * gg.y + bb.y);
    __half2 h1 = __floats2half2_rn((v.z - mean) * inv * gg.z + bb.z,
                                   (v.w - mean) * inv * gg.w + bb.w);
    __half2* dst = (__half2*)(out + (size_t)row * D_EMB + tid * 4);
    dst[0] = h0; dst[1] = h1;
}

// ---------------- pack w_qkv [H][D][192] -> [D][H*192], half ----------------
__global__ void __launch_bounds__(256) repack_qkv_kernel(const float* __restrict__ w,
                                                         __half* __restrict__ wp) {
    int i = blockIdx.x * 256 + threadIdx.x;
    int n4 = i % 768, d = i / 768;
    int n = n4 * 4;
    int h = n / 192, f = n - h * 192;
    float4 v = *(const float4*)&w[((size_t)h * D_EMB + d) * 192 + f];
    __half2* dst = (__half2*)&wp[(size_t)d * 3072 + n];
    dst[0] = __floats2half2_rn(v.x, v.y);
    dst[1] = __floats2half2_rn(v.z, v.w);
}

// ---------------- generic f32 -> f16 (n4 = count/4 float4s) ----------------
__global__ void __launch_bounds__(256) f2h_kernel(const float* __restrict__ in,
                                                  __half* __restrict__ out) {
    int i = blockIdx.x * 256 + threadIdx.x;
    float4 v = ((const float4*)in)[i];
    __half2* dst = (__half2*)(out + (size_t)i * 4);
    dst[0] = __floats2half2_rn(v.x, v.y);
    dst[1] = __floats2half2_rn(v.z, v.w);
}

// ---------------- Fuse W2 = blockdiag(w_hproj) @ w_out -> half ----------------
__global__ void __launch_bounds__(256) fuse_w2_kernel(const float* __restrict__ whp,
                                                      const float* __restrict__ wout,
                                                      __half* __restrict__ W2) {
    __shared__ float hp[64 * 64];
    __shared__ float wo[64 * 64];
    int h = blockIdx.x, nt = blockIdx.y, tid = threadIdx.x;
#pragma unroll
    for (int j = 0; j < 4; j++) {
        int f = tid + 256 * j;
        ((float4*)hp)[f] = ((const float4*)(whp + (size_t)h * 4096))[f];
        int r = f >> 4, c4 = f & 15;
        *(float4*)&wo[r * 64 + c4 * 4] =
            *(const float4*)&wout[(size_t)(h * 64 + r) * D_EMB + nt * 64 + c4 * 4];
    }
    __syncthreads();
    int ty = tid >> 4, tx = tid & 15;
#pragma unroll
    for (int i = 0; i < 4; i++) {
        int d = ty * 4 + i;
#pragma unroll
        for (int j = 0; j < 4; j++) {
            int e = tx * 4 + j;
            float acc = 0.f;
#pragma unroll 8
            for (int k = 0; k < 64; k++) acc += hp[d * 64 + k] * wo[k * 64 + e];
            W2[(size_t)(h * 64 + d) * D_EMB + nt * 64 + e] = __float2half_rn(acc);
        }
    }
}

// bias2[e] = b_out[e] + sum_i b_hproj_flat[i] * w_out[i][e]
__global__ void __launch_bounds__(256) bias2_kernel(const float* __restrict__ bhp,
                                                    const float* __restrict__ bout,
                                                    const float* __restrict__ wout,
                                                    float* __restrict__ b2) {
    __shared__ float part[16][16];
    int tid = threadIdx.x;
    int ec = tid & 15;
    int e = blockIdx.x * 16 + ec;
    int chunk = tid >> 4;
    float acc = 0.f;
    int i0 = chunk * 64;
#pragma unroll 8
    for (int i = i0; i < i0 + 64; i++) acc += bhp[i] * wout[(size_t)i * D_EMB + e];
    part[chunk][ec] = acc;
    __syncthreads();
    if (chunk == 0) {
        float s = bout[e];
#pragma unroll
        for (int cch = 0; cch < 16; cch++) s += part[cch][ec];
        b2[e] = s;
    }
}

// ---------------- fp16 tensor-core GEMM 128x128x32, 3-stage, ldmatrix ----------------
#define BM 128
#define BN 128
#define BK 32
#define NSTG 3
#define A_STR 40     // 32 + 8 halfs pad (row 80B: conflict-free ldmatrix)
#define B_STR 136    // 128 + 8 halfs pad (row 272B: conflict-free ldmatrix.trans)
#define GEMM_SMEM ((NSTG * (BM * A_STR + BK * B_STR)) * 2)

// EPI 0: qkv scatter (tfr f32), EPI 1: +bias +res -> f32, EPI 2: gelu+bias -> half
template <int EPI>
__global__ void __launch_bounds__(256, 2) gemm_h(
    const __half* __restrict__ A, const __half* __restrict__ B,
    int M, int N, int K,
    const float* __restrict__ bias, const float* __restrict__ res,
    float* __restrict__ outf, __half* __restrict__ outh,
    float* __restrict__ oq, float* __restrict__ okk, float* __restrict__ ov) {
    extern __shared__ __half smh[];
    __half (*As)[BM][A_STR] = (__half (*)[BM][A_STR])smh;
    __half (*Bs)[BK][B_STR] = (__half (*)[BK][B_STR])(smh + NSTG * BM * A_STR);

    int tid = threadIdx.x;
    int lane = tid & 31, warp = tid >> 5;
    int wm = (warp >> 2) * 64, wn = (warp & 3) * 32;
    int bm = blockIdx.x * BM, bn = blockIdx.y * BN;

    float acc[4][4][4];
#pragma unroll
    for (int mi = 0; mi < 4; mi++)
#pragma unroll
        for (int ni = 0; ni < 4; ni++)
#pragma unroll
            for (int q = 0; q < 4; q++) acc[mi][ni][q] = 0.f;

    const __half* Ag = A + (size_t)bm * K;
    const __half* Bg = B + bn;
    // A tile: 128 x 32h (64B/row = 4 x 16B); 512 chunks, 2/thread
    int a_row = tid >> 2, a_c8 = (tid & 3) * 8;
    // B tile: 32 x 128h (256B/row = 16 x 16B); 512 chunks, 2/thread
    int b_row = tid >> 4, b_c8 = (tid & 15) * 8;

    int T = K / BK;
#pragma unroll
    for (int p = 0; p < NSTG - 1; p++) {
        int k0 = p * BK;
        cpasync16(&As[p][a_row][a_c8], Ag + (size_t)a_row * K + k0 + a_c8);
        cpasync16(&As[p][a_row + 64][a_c8], Ag + (size_t)(a_row + 64) * K + k0 + a_c8);
        cpasync16(&Bs[p][b_row][b_c8], Bg + (size_t)(k0 + b_row) * N + b_c8);
        cpasync16(&Bs[p][b_row + 16][b_c8], Bg + (size_t)(k0 + b_row + 16) * N + b_c8);
        cpcommit();
    }

    // ldmatrix thread->address components
    int lrow = lane & 15;           // row within 16-row group
    int lhi = (lane >> 4) & 1;      // selects +8 column chunk
    int r = lane >> 2, c = lane & 3;

    int buf = 0, nstage = NSTG - 1;
    for (int t = 0; t < T; t++) {
        if (t < T - 1) cpwait1(); else cpwait0();
        __syncthreads();
        if (t + 2 < T) {
            int k0 = (t + 2) * BK;
            int s = nstage;
            cpasync16(&As[s][a_row][a_c8], Ag + (size_t)a_row * K + k0 + a_c8);
            cpasync16(&As[s][a_row + 64][a_c8], Ag + (size_t)(a_row + 64) * K + k0 + a_c8);
            cpasync16(&Bs[s][b_row][b_c8], Bg + (size_t)(k0 + b_row) * N + b_c8);
            cpasync16(&Bs[s][b_row + 16][b_c8], Bg + (size_t)(k0 + b_row + 16) * N + b_c8);
            cpcommit();
        }
        nstage = buf;

        unsigned abase = (unsigned)__cvta_generic_to_shared(&As[buf][0][0]);
        unsigned bbase = (unsigned)__cvta_generic_to_shared(&Bs[buf][0][0]);
#pragma unroll
        for (int ks = 0; ks < 2; ks++) {
            int k0 = ks * 16;
            unsigned a[4][4], bq[4][2];
#pragma unroll
            for (int mi = 0; mi < 4; mi++) {
                unsigned ad = abase +
                    (((wm + mi * 16 + lrow) * A_STR) + k0 + lhi * 8) * 2;
                ldsm4(a[mi], ad);
            }
#pragma unroll
            for (int np = 0; np < 2; np++) {
                unsigned tmp[4];
                unsigned bd = bbase +
                    (((k0 + lrow) * B_STR) + wn + np * 16 + lhi * 8) * 2;
                ldsm4t(tmp, bd);
                bq[np * 2][0] = tmp[0]; bq[np * 2][1] = tmp[1];
                bq[np * 2 + 1][0] = tmp[2]; bq[np * 2 + 1][1] = tmp[3];
            }
#pragma unroll
            for (int mi = 0; mi < 4; mi++)
#pragma unroll
                for (int ni = 0; ni < 4; ni++) mma16h(acc[mi][ni], a[mi], bq[ni]);
        }
        buf = (buf + 1 == NSTG) ? 0 : buf + 1;
    }

    int c2 = c * 2;
#pragma unroll
    for (int mi = 0; mi < 4; mi++) {
        int row0 = bm + wm + mi * 16 + r;
        int row1 = row0 + 8;
#pragma unroll
        for (int ni = 0; ni < 4; ni++) {
            int col = bn + wn + ni * 8 + c2;
            float v00 = acc[mi][ni][0], v01 = acc[mi][ni][1];
            float v10 = acc[mi][ni][2], v11 = acc[mi][ni][3];
            if (EPI == 0) {
                int h = col / 192;
                int f = col - h * 192;
                int which = f >> 6;
                int d = f & 63;
                float* dst = (which == 0) ? oq : (which == 1) ? okk : ov;
                {
                    int b_ = row0 >> 11, s_ = row0 & 2047;
                    size_t base = (((size_t)(b_ * 16 + h) * S_SEQ + s_) * HD + d);
                    dst[base] = tfr(v00);
                    dst[base + 1] = tfr(v01);
                }
                {
                    int b_ = row1 >> 11, s_ = row1 & 2047;
                    size_t base = (((size_t)(b_ * 16 + h) * S_SEQ + s_) * HD + d);
                    dst[base] = tfr(v10);
                    dst[base + 1] = tfr(v11);
                }
            } else if (EPI == 1) {
                float2 bv = *(const float2*)&bias[col];
                float2 r0 = *(const float2*)&res[(size_t)row0 * N + col];
                float2 r1 = *(const float2*)&res[(size_t)row1 * N + col];
                float2 o0, o1;
                o0.x = v00 + bv.x + r0.x; o0.y = v01 + bv.y + r0.y;
                o1.x = v10 + bv.x + r1.x; o1.y = v11 + bv.y + r1.y;
                *(float2*)&outf[(size_t)row0 * N + col] = o0;
                *(float2*)&outf[(size_t)row1 * N + col] = o1;
            } else {
                float2 bv = *(const float2*)&bias[col];
                *(__half2*)&outh[(size_t)row0 * N + col] =
                    __floats2half2_rn(geluf(v00 + bv.x), geluf(v01 + bv.y));
                *(__half2*)&outh[(size_t)row1 * N + col] =
                    __floats2half2_rn(geluf(v10 + bv.x), geluf(v11 + bv.y));
            }
        }
    }
}

// ---------------- Tensor-core flash attention (tf32, unchanged core) ----------------
#define KS_STR 68
#define VS_STR 72
#define PS_STR 68
#define ATT_SMEM_BYTES ((2 * 64 * KS_STR + 2 * 64 * VS_STR + 64 * PS_STR) * 4)

__global__ void __launch_bounds__(128) attn_tc(const float* __restrict__ Qg,
                                               const float* __restrict__ Kg,
                                               const float* __restrict__ Vg,
                                               __half* __restrict__ Og) {
    extern __shared__ float sm[];
    float* Ks = sm;
    float* Vs = sm + 2 * 64 * KS_STR;
    float* Ps = Vs + 2 * 64 * VS_STR;

    int tid = threadIdx.x, lane = tid & 31, warp = tid >> 5;
    int r = lane >> 2, cq = lane & 3;
    int q0 = blockIdx.x * 64, bh = blockIdx.y;
    const float* qp = Qg + (size_t)bh * S_SEQ * HD;
    const float* kp = Kg + (size_t)bh * S_SEQ * HD;
    const float* vp = Vg + (size_t)bh * S_SEQ * HD;

#pragma unroll
    for (int j = 0; j < 8; j++) {
        int f = tid + 128 * j;
        int row = f >> 4, c4 = (f & 15) * 4;
        *(float4*)&Ps[row * PS_STR + c4] = *(const float4*)&qp[(size_t)(q0 + row) * HD + c4];
    }
    __syncthreads();
    unsigned qa[8][4];
    int qrow = warp * 16 + r;
#pragma unroll
    for (int kf = 0; kf < 8; kf++) {
        qa[kf][0] = __float_as_uint(Ps[qrow * PS_STR + kf * 8 + cq] * 0.125f);
        qa[kf][1] = __float_as_uint(Ps[(qrow + 8) * PS_STR + kf * 8 + cq] * 0.125f);
        qa[kf][2] = __float_as_uint(Ps[qrow * PS_STR + kf * 8 + 4 + cq] * 0.125f);
        qa[kf][3] = __float_as_uint(Ps[(qrow + 8) * PS_STR + kf * 8 + 4 + cq] * 0.125f);
    }
    __syncthreads();

    float m0 = -1e30f, m1 = -1e30f, l0 = 0.f, l1 = 0.f;
    float oacc[8][4];
#pragma unroll
    for (int ni = 0; ni < 8; ni++)
#pragma unroll
        for (int q = 0; q < 4; q++) oacc[ni][q] = 0.f;

    {
#pragma unroll
        for (int j = 0; j < 8; j++) {
            int f = tid + 128 * j;
            int row = f >> 4, c4 = (f & 15) * 4;
            cpasync16(&Ks[row * KS_STR + c4], &kp[(size_t)row * HD + c4]);
            cpasync16(&Vs[row * VS_STR + c4], &vp[(size_t)row * HD + c4]);
        }
        cpcommit();
    }

    const int NT = S_SEQ / 64;
    for (int kt = 0; kt < NT; kt++) {
        int buf = kt & 1;
        if (kt + 1 < NT) {
            int nb = 1 - buf;
            const float* kg = kp + (size_t)(kt + 1) * 64 * HD;
            const float* vg = vp + (size_t)(kt + 1) * 64 * HD;
            float* kd = Ks + nb * 64 * KS_STR;
            float* vd = Vs + nb * 64 * VS_STR;
#pragma unroll
            for (int j = 0; j < 8; j++) {
                int f = tid + 128 * j;
                int row = f >> 4, c4 = (f & 15) * 4;
                cpasync16(&kd[row * KS_STR + c4], &kg[(size_t)row * HD + c4]);
                cpasync16(&vd[row * VS_STR + c4], &vg[(size_t)row * HD + c4]);
            }
            cpcommit();
            cpwait1();
        } else {
            cpwait0();
        }
        __syncthreads();
        const float* kb = Ks + buf * 64 * KS_STR;
        const float* vb = Vs + buf * 64 * VS_STR;

        float s[8][4];
#pragma unroll
        for (int ni = 0; ni < 8; ni++)
#pragma unroll
            for (int q = 0; q < 4; q++) s[ni][q] = 0.f;
#pragma unroll
        for (int kf = 0; kf < 8; kf++) {
#pragma unroll
            for (int ni = 0; ni < 8; ni++) {
                unsigned bb[2];
                bb[0] = __float_as_uint(kb[(r + 8 * ni) * KS_STR + kf * 8 + cq]);
                bb[1] = __float_as_uint(kb[(r + 8 * ni) * KS_STR + kf * 8 + 4 + cq]);
                mma8(s[ni], qa[kf], bb);
            }
        }

        float rm0 = -1e30f, rm1 = -1e30f;
#pragma unroll
        for (int ni = 0; ni < 8; ni++) {
            rm0 = fmaxf(rm0, fmaxf(s[ni][0], s[ni][1]));
            rm1 = fmaxf(rm1, fmaxf(s[ni][2], s[ni][3]));
        }
        rm0 = fmaxf(rm0, __shfl_xor_sync(0xffffffffu, rm0, 1));
        rm0 = fmaxf(rm0, __shfl_xor_sync(0xffffffffu, rm0, 2));
        rm1 = fmaxf(rm1, __shfl_xor_sync(0xffffffffu, rm1, 1));
        rm1 = fmaxf(rm1, __shfl_xor_sync(0xffffffffu, rm1, 2));
        float mn0 = fmaxf(m0, rm0), mn1 = fmaxf(m1, rm1);
        float corr0 = __expf(m0 - mn0), corr1 = __expf(m1 - mn1);
        m0 = mn0; m1 = mn1;
        float rs0 = 0.f, rs1 = 0.f;
#pragma unroll
        for (int ni = 0; ni < 8; ni++) {
            float p0 = __expf(s[ni][0] - mn0);
            float p1 = __expf(s[ni][1] - mn0);
            float p2 = __expf(s[ni][2] - mn1);
            float p3 = __expf(s[ni][3] - mn1);
            rs0 += p0 + p1; rs1 += p2 + p3;
            float2 w0; w0.x = tfr(p0); w0.y = tfr(p1);
            float2 w1; w1.x = tfr(p2); w1.y = tfr(p3);
            *(float2*)&Ps[qrow * PS_STR + ni * 8 + 2 * cq] = w0;
            *(float2*)&Ps[(qrow + 8) * PS_STR + ni * 8 + 2 * cq] = w1;
        }
        rs0 += __shfl_xor_sync(0xffffffffu, rs0, 1);
        rs0 += __shfl_xor_sync(0xffffffffu, rs0, 2);
        rs1 += __shfl_xor_sync(0xffffffffu, rs1, 1);
        rs1 += __shfl_xor_sync(0xffffffffu, rs1, 2);
        l0 = l0 * corr0 + rs0;
        l1 = l1 * corr1 + rs1;
#pragma unroll
        for (int ni = 0; ni < 8; ni++) {
            oacc[ni][0] *= corr0; oacc[ni][1] *= corr0;
            oacc[ni][2] *= corr1; oacc[ni][3] *= corr1;
        }
        __syncwarp();

#pragma unroll
        for (int kf = 0; kf < 8; kf++) {
            unsigned pa[4];
            pa[0] = __float_as_uint(Ps[qrow * PS_STR + kf * 8 + cq]);
            pa[1] = __float_as_uint(Ps[(qrow + 8) * PS_STR + kf * 8 + cq]);
            pa[2] = __float_as_uint(Ps[qrow * PS_STR + kf * 8 + 4 + cq]);
            pa[3] = __float_as_uint(Ps[(qrow + 8) * PS_STR + kf * 8 + 4 + cq]);
#pragma unroll
            for (int ni = 0; ni < 8; ni++) {
                unsigned bb[2];
                bb[0] = __float_as_uint(vb[(kf * 8 + cq) * VS_STR + r + 8 * ni]);
                bb[1] = __float_as_uint(vb[(kf * 8 + 4 + cq) * VS_STR + r + 8 * ni]);
                mma8(oacc[ni], pa, bb);
            }
        }
        __syncthreads();
    }

    // normalize + write concat-head layout as half (feeds proj GEMM A)
    int b_ = bh >> 4, h = bh & 15;
    float inv0 = 1.0f / l0, inv1 = 1.0f / l1;
    size_t t0 = ((size_t)b_ * S_SEQ + q0 + qrow) * D_EMB + h * HD;
    size_t t1 = ((size_t)b_ * S_SEQ + q0 + qrow + 8) * D_EMB + h * HD;
#pragma unroll
    for (int ni = 0; ni < 8; ni++) {
        int d = ni * 8 + 2 * cq;
        *(__half2*)&Og[t0 + d] = __floats2half2_rn(oacc[ni][0] * inv0, oacc[ni][1] * inv0);
        *(__half2*)&Og[t1 + d] = __floats2half2_rn(oacc[ni][2] * inv1, oacc[ni][3] * inv1);
    }
}

// ---------------- launch ----------------
extern "C" void kernel_launch(void* const* d_in, const int* in_sizes, int n_in,
                              void* d_out, int out_size) {
    const float* x = (const float*)d_in[0];
    const float* w_qkv = (const float*)d_in[1];
    const float* w_hproj = (const float*)d_in[2];
    const float* b_hproj = (const float*)d_in[3];
    const float* w_out = (const float*)d_in[4];
    const float* b_out = (const float*)d_in[5];
    const float* w_fc1 = (const float*)d_in[6];
    const float* b_fc1 = (const float*)d_in[7];
    const float* w_fc2 = (const float*)d_in[8];
    const float* b_fc2 = (const float*)d_in[9];
    const float* g1 = (const float*)d_in[10];
    const float* be1 = (const float*)d_in[11];
    const float* g2 = (const float*)d_in[12];
    const float* be2 = (const float*)d_in[13];
    float* out = (float*)d_out;

    __half *xnh, *oh, *hh, *W2h, *wqkvph, *wf1h, *wf2h;
    float *q, *k, *v, *x1, *b2;
    cudaGetSymbolAddress((void**)&xnh, g_xnh);
    cudaGetSymbolAddress((void**)&q, g_q);
    cudaGetSymbolAddress((void**)&k, g_k);
    cudaGetSymbolAddress((void**)&v, g_v);
    cudaGetSymbolAddress((void**)&oh, g_oh);
    cudaGetSymbolAddress((void**)&x1, g_x1);
    cudaGetSymbolAddress((void**)&hh, g_hh);
    cudaGetSymbolAddress((void**)&W2h, g_W2h);
    cudaGetSymbolAddress((void**)&b2, g_b2);
    cudaGetSymbolAddress((void**)&wqkvph, g_wqkvph);
    cudaGetSymbolAddress((void**)&wf1h, g_wf1h);
    cudaGetSymbolAddress((void**)&wf2h, g_wf2h);

    cudaFuncSetAttribute(attn_tc, cudaFuncAttributeMaxDynamicSharedMemorySize,
                         ATT_SMEM_BYTES);
    cudaFuncSetAttribute(gemm_h<0>, cudaFuncAttributeMaxDynamicSharedMemorySize, GEMM_SMEM);
    cudaFuncSetAttribute(gemm_h<1>, cudaFuncAttributeMaxDynamicSharedMemorySize, GEMM_SMEM);
    cudaFuncSetAttribute(gemm_h<2>, cudaFuncAttributeMaxDynamicSharedMemorySize, GEMM_SMEM);

    // LN1 + weight prep (independent)
    ln_kernel<<<T_TOK, 256>>>(x, g1, be1, xnh);
    repack_qkv_kernel<<<3072, 256>>>(w_qkv, wqkvph);
    fuse_w2_kernel<<<dim3(16, 16), 256>>>(w_hproj, w_out, W2h);
    bias2_kernel<<<64, 256>>>(b_hproj, b_out, w_out, b2);
    f2h_kernel<<<4096, 256>>>(w_fc1, wf1h);
    f2h_kernel<<<4096, 256>>>(w_fc2, wf2h);
    // QKV: [4096,1024] x [1024,3072] fp16 -> q/k/v (tf32-rounded f32)
    gemm_h<0><<<dim3(32, 24), 256, GEMM_SMEM>>>(xnh, wqkvph, T_TOK, 3072, D_EMB,
                                                nullptr, nullptr, nullptr, nullptr, q, k, v);
    // flash attention (tf32) -> concat-head half
    attn_tc<<<dim3(S_SEQ / 64, 32), 128, ATT_SMEM_BYTES>>>(q, k, v, oh);
    // out projection + bias2 + residual -> x1 (f32)
    gemm_h<1><<<dim3(32, 8), 256, GEMM_SMEM>>>(oh, W2h, T_TOK, D_EMB, D_EMB,
                                               b2, x, x1, nullptr, nullptr, nullptr, nullptr);
    // LN2
    ln_kernel<<<T_TOK, 256>>>(x1, g2, be2, xnh);
    // FC1 + bias + exact GELU -> half
    gemm_h<2><<<dim3(32, 32), 256, GEMM_SMEM>>>(xnh, wf1h, T_TOK, MLP_DIM, D_EMB,
                                                b_fc1, nullptr, nullptr, hh,
                                                nullptr, nullptr, nullptr);
    // FC2 + bias + residual x1 -> out (f32)
    gemm_h<1><<<dim3(32, 8), 256, GEMM_SMEM>>>(hh, wf2h, T_TOK, D_EMB, MLP_DIM,
                                               b_fc2, x1, out, nullptr,
                                               nullptr, nullptr, nullptr);
}

// round 7
// speedup vs baseline: 6.3191x; 1.2813x over previous
#include <cuda_runtime.h>
#include <cuda_fp16.h>
#include <math.h>

#define T_TOK 4096
#define D_EMB 1024
#define S_SEQ 2048
#define NH 16
#define HD 64
#define MLP_DIM 4096

// -------- scratch (device globals; no allocation allowed) --------
__device__ __half g_xnh[T_TOK * D_EMB];
__device__ __half g_qh[32 * S_SEQ * HD];
__device__ __half g_kh[32 * S_SEQ * HD];
__device__ __half g_vh[32 * S_SEQ * HD];
__device__ __half g_oh[T_TOK * D_EMB];
__device__ float g_x1[T_TOK * D_EMB];
__device__ __half g_hh[T_TOK * MLP_DIM];
__device__ __half g_W2h[D_EMB * D_EMB];
__device__ float g_b2[D_EMB];
__device__ __half g_wqkvph[D_EMB * 3 * HD * NH];   // [1024][3072]
__device__ __half g_wf1h[D_EMB * MLP_DIM];
__device__ __half g_wf2h[MLP_DIM * D_EMB];

// ---------------- helpers ----------------
__device__ __forceinline__ float geluf(float x) {
    return 0.5f * x * (1.0f + erff(x * 0.70710678118654752f));
}
__device__ __forceinline__ void cpasync16(void* s, const void* g) {
    unsigned sa = (unsigned)__cvta_generic_to_shared(s);
    asm volatile("cp.async.cg.shared.global [%0], [%1], 16;" :: "r"(sa), "l"(g));
}
__device__ __forceinline__ void cpcommit() { asm volatile("cp.async.commit_group;"); }
__device__ __forceinline__ void cpwait0() { asm volatile("cp.async.wait_group 0;"); }
__device__ __forceinline__ void cpwait1() { asm volatile("cp.async.wait_group 1;"); }
__device__ __forceinline__ void mma16h(float* d, const unsigned* a, const unsigned* b) {
    asm volatile(
        "mma.sync.aligned.m16n8k16.row.col.f32.f16.f16.f32 "
        "{%0,%1,%2,%3},{%4,%5,%6,%7},{%8,%9},{%0,%1,%2,%3};"
        : "+f"(d[0]), "+f"(d[1]), "+f"(d[2]), "+f"(d[3])
        : "r"(a[0]), "r"(a[1]), "r"(a[2]), "r"(a[3]), "r"(b[0]), "r"(b[1]));
}
__device__ __forceinline__ void ldsm4(unsigned* r, unsigned addr) {
    asm volatile("ldmatrix.sync.aligned.m8n8.x4.shared.b16 {%0,%1,%2,%3}, [%4];"
        : "=r"(r[0]), "=r"(r[1]), "=r"(r[2]), "=r"(r[3]) : "r"(addr));
}
__device__ __forceinline__ void ldsm4t(unsigned* r, unsigned addr) {
    asm volatile("ldmatrix.sync.aligned.m8n8.x4.trans.shared.b16 {%0,%1,%2,%3}, [%4];"
        : "=r"(r[0]), "=r"(r[1]), "=r"(r[2]), "=r"(r[3]) : "r"(addr));
}

// ---------------- LayerNorm -> half ----------------
__global__ void __launch_bounds__(256) ln_kernel(const float* __restrict__ in,
                                                 const float* __restrict__ g,
                                                 const float* __restrict__ b,
                                                 __half* __restrict__ out) {
    __shared__ float s_sum[256], s_sq[256];
    int row = blockIdx.x, tid = threadIdx.x;
    float4 v = ((const float4*)(in + (size_t)row * D_EMB))[tid];
    s_sum[tid] = v.x + v.y + v.z + v.w;
    s_sq[tid] = v.x * v.x + v.y * v.y + v.z * v.z + v.w * v.w;
    __syncthreads();
    for (int s = 128; s > 0; s >>= 1) {
        if (tid < s) { s_sum[tid] += s_sum[tid + s]; s_sq[tid] += s_sq[tid + s]; }
        __syncthreads();
    }
    float mean = s_sum[0] * (1.0f / D_EMB);
    float var = s_sq[0] * (1.0f / D_EMB) - mean * mean;
    float inv = rsqrtf(var + 1e-5f);
    float4 gg = ((const float4*)g)[tid];
    float4 bb = ((const float4*)b)[tid];
    __half2 h0 = __floats2half2_rn((v.x - mean) * inv * gg.x + bb.x,
                                   (v.y - mean) * inv * gg.y + bb.y);
    __half2 h1 = __floats2half2_rn((v.z - mean) * inv * gg.z + bb.z,
                                   (v.w - mean) * inv * gg.w + bb.w);
    __half2* dst = (__half2*)(out + (size_t)row * D_EMB + tid * 4);
    dst[0] = h0; dst[1] = h1;
}

// ---------------- pack w_qkv [H][D][192] -> [D][H*192], half ----------------
__global__ void __launch_bounds__(256) repack_qkv_kernel(const float* __restrict__ w,
                                                         __half* __restrict__ wp) {
    int i = blockIdx.x * 256 + threadIdx.x;
    int n4 = i % 768, d = i / 768;
    int n = n4 * 4;
    int h = n / 192, f = n - h * 192;
    float4 v = *(const float4*)&w[((size_t)h * D_EMB + d) * 192 + f];
    __half2* dst = (__half2*)&wp[(size_t)d * 3072 + n];
    dst[0] = __floats2half2_rn(v.x, v.y);
    dst[1] = __floats2half2_rn(v.z, v.w);
}

// ---------------- generic f32 -> f16 ----------------
__global__ void __launch_bounds__(256) f2h_kernel(const float* __restrict__ in,
                                                  __half* __restrict__ out) {
    int i = blockIdx.x * 256 + threadIdx.x;
    float4 v = ((const float4*)in)[i];
    __half2* dst = (__half2*)(out + (size_t)i * 4);
    dst[0] = __floats2half2_rn(v.x, v.y);
    dst[1] = __floats2half2_rn(v.z, v.w);
}

// ---------------- Fuse W2 = blockdiag(w_hproj) @ w_out -> half ----------------
__global__ void __launch_bounds__(256) fuse_w2_kernel(const float* __restrict__ whp,
                                                      const float* __restrict__ wout,
                                                      __half* __restrict__ W2) {
    __shared__ float hp[64 * 64];
    __shared__ float wo[64 * 64];
    int h = blockIdx.x, nt = blockIdx.y, tid = threadIdx.x;
#pragma unroll
    for (int j = 0; j < 4; j++) {
        int f = tid + 256 * j;
        ((float4*)hp)[f] = ((const float4*)(whp + (size_t)h * 4096))[f];
        int r = f >> 4, c4 = f & 15;
        *(float4*)&wo[r * 64 + c4 * 4] =
            *(const float4*)&wout[(size_t)(h * 64 + r) * D_EMB + nt * 64 + c4 * 4];
    }
    __syncthreads();
    int ty = tid >> 4, tx = tid & 15;
#pragma unroll
    for (int i = 0; i < 4; i++) {
        int d = ty * 4 + i;
#pragma unroll
        for (int j = 0; j < 4; j++) {
            int e = tx * 4 + j;
            float acc = 0.f;
#pragma unroll 8
            for (int k = 0; k < 64; k++) acc += hp[d * 64 + k] * wo[k * 64 + e];
            W2[(size_t)(h * 64 + d) * D_EMB + nt * 64 + e] = __float2half_rn(acc);
        }
    }
}

// bias2[e] = b_out[e] + sum_i b_hproj_flat[i] * w_out[i][e]
__global__ void __launch_bounds__(256) bias2_kernel(const float* __restrict__ bhp,
                                                    const float* __restrict__ bout,
                                                    const float* __restrict__ wout,
                                                    float* __restrict__ b2) {
    __shared__ float part[16][16];
    int tid = threadIdx.x;
    int ec = tid & 15;
    int e = blockIdx.x * 16 + ec;
    int chunk = tid >> 4;
    float acc = 0.f;
    int i0 = chunk * 64;
#pragma unroll 8
    for (int i = i0; i < i0 + 64; i++) acc += bhp[i] * wout[(size_t)i * D_EMB + e];
    part[chunk][ec] = acc;
    __syncthreads();
    if (chunk == 0) {
        float s = bout[e];
#pragma unroll
        for (int cch = 0; cch < 16; cch++) s += part[cch][ec];
        b2[e] = s;
    }
}

// ---------------- fp16 tensor-core GEMM 128x128x32, 3-stage, ldmatrix ----------------
#define BM 128
#define BN 128
#define BK 32
#define NSTG 3
#define A_STR 40
#define B_STR 136
#define GEMM_SMEM ((NSTG * (BM * A_STR + BK * B_STR)) * 2)

// EPI 0: qkv scatter -> half, EPI 1: +bias +res -> f32, EPI 2: gelu+bias -> half
template <int EPI>
__global__ void __launch_bounds__(256, 2) gemm_h(
    const __half* __restrict__ A, const __half* __restrict__ B,
    int M, int N, int K,
    const float* __restrict__ bias, const float* __restrict__ res,
    float* __restrict__ outf, __half* __restrict__ outh,
    __half* __restrict__ oq, __half* __restrict__ okk, __half* __restrict__ ov) {
    extern __shared__ __half smh[];
    __half (*As)[BM][A_STR] = (__half (*)[BM][A_STR])smh;
    __half (*Bs)[BK][B_STR] = (__half (*)[BK][B_STR])(smh + NSTG * BM * A_STR);

    int tid = threadIdx.x;
    int lane = tid & 31, warp = tid >> 5;
    int wm = (warp >> 2) * 64, wn = (warp & 3) * 32;
    int bm = blockIdx.x * BM, bn = blockIdx.y * BN;

    float acc[4][4][4];
#pragma unroll
    for (int mi = 0; mi < 4; mi++)
#pragma unroll
        for (int ni = 0; ni < 4; ni++)
#pragma unroll
            for (int q = 0; q < 4; q++) acc[mi][ni][q] = 0.f;

    const __half* Ag = A + (size_t)bm * K;
    const __half* Bg = B + bn;
    int a_row = tid >> 2, a_c8 = (tid & 3) * 8;
    int b_row = tid >> 4, b_c8 = (tid & 15) * 8;

    int T = K / BK;
#pragma unroll
    for (int p = 0; p < NSTG - 1; p++) {
        int k0 = p * BK;
        cpasync16(&As[p][a_row][a_c8], Ag + (size_t)a_row * K + k0 + a_c8);
        cpasync16(&As[p][a_row + 64][a_c8], Ag + (size_t)(a_row + 64) * K + k0 + a_c8);
        cpasync16(&Bs[p][b_row][b_c8], Bg + (size_t)(k0 + b_row) * N + b_c8);
        cpasync16(&Bs[p][b_row + 16][b_c8], Bg + (size_t)(k0 + b_row + 16) * N + b_c8);
        cpcommit();
    }

    int lrow = lane & 15;
    int lhi = (lane >> 4) & 1;
    int r = lane >> 2, c = lane & 3;

    int buf = 0, nstage = NSTG - 1;
    for (int t = 0; t < T; t++) {
        if (t < T - 1) cpwait1(); else cpwait0();
        __syncthreads();
        if (t + 2 < T) {
            int k0 = (t + 2) * BK;
            int s = nstage;
            cpasync16(&As[s][a_row][a_c8], Ag + (size_t)a_row * K + k0 + a_c8);
            cpasync16(&As[s][a_row + 64][a_c8], Ag + (size_t)(a_row + 64) * K + k0 + a_c8);
            cpasync16(&Bs[s][b_row][b_c8], Bg + (size_t)(k0 + b_row) * N + b_c8);
            cpasync16(&Bs[s][b_row + 16][b_c8], Bg + (size_t)(k0 + b_row + 16) * N + b_c8);
            cpcommit();
        }
        nstage = buf;

        unsigned abase = (unsigned)__cvta_generic_to_shared(&As[buf][0][0]);
        unsigned bbase = (unsigned)__cvta_generic_to_shared(&Bs[buf][0][0]);
#pragma unroll
        for (int ks = 0; ks < 2; ks++) {
            int k0 = ks * 16;
            unsigned a[4][4], bq[4][2];
#pragma unroll
            for (int mi = 0; mi < 4; mi++) {
                unsigned ad = abase +
                    (((wm + mi * 16 + lrow) * A_STR) + k0 + lhi * 8) * 2;
                ldsm4(a[mi], ad);
            }
#pragma unroll
            for (int np = 0; np < 2; np++) {
                unsigned tmp[4];
                unsigned bd = bbase +
                    (((k0 + lrow) * B_STR) + wn + np * 16 + lhi * 8) * 2;
                ldsm4t(tmp, bd);
                bq[np * 2][0] = tmp[0]; bq[np * 2][1] = tmp[1];
                bq[np * 2 + 1][0] = tmp[2]; bq[np * 2 + 1][1] = tmp[3];
            }
#pragma unroll
            for (int mi = 0; mi < 4; mi++)
#pragma unroll
                for (int ni = 0; ni < 4; ni++) mma16h(acc[mi][ni], a[mi], bq[ni]);
        }
        buf = (buf + 1 == NSTG) ? 0 : buf + 1;
    }

    int c2 = c * 2;
#pragma unroll
    for (int mi = 0; mi < 4; mi++) {
        int row0 = bm + wm + mi * 16 + r;
        int row1 = row0 + 8;
#pragma unroll
        for (int ni = 0; ni < 4; ni++) {
            int col = bn + wn + ni * 8 + c2;
            float v00 = acc[mi][ni][0], v01 = acc[mi][ni][1];
            float v10 = acc[mi][ni][2], v11 = acc[mi][ni][3];
            if (EPI == 0) {
                int h = col / 192;
                int f = col - h * 192;
                int which = f >> 6;
                int d = f & 63;
                __half* dst = (which == 0) ? oq : (which == 1) ? okk : ov;
                {
                    int b_ = row0 >> 11, s_ = row0 & 2047;
                    size_t base = (((size_t)(b_ * 16 + h) * S_SEQ + s_) * HD + d);
                    *(__half2*)&dst[base] = __floats2half2_rn(v00, v01);
                }
                {
                    int b_ = row1 >> 11, s_ = row1 & 2047;
                    size_t base = (((size_t)(b_ * 16 + h) * S_SEQ + s_) * HD + d);
                    *(__half2*)&dst[base] = __floats2half2_rn(v10, v11);
                }
            } else if (EPI == 1) {
                float2 bv = *(const float2*)&bias[col];
                float2 r0 = *(const float2*)&res[(size_t)row0 * N + col];
                float2 r1 = *(const float2*)&res[(size_t)row1 * N + col];
                float2 o0, o1;
                o0.x = v00 + bv.x + r0.x; o0.y = v01 + bv.y + r0.y;
                o1.x = v10 + bv.x + r1.x; o1.y = v11 + bv.y + r1.y;
                *(float2*)&outf[(size_t)row0 * N + col] = o0;
                *(float2*)&outf[(size_t)row1 * N + col] = o1;
            } else {
                float2 bv = *(const float2*)&bias[col];
                *(__half2*)&outh[(size_t)row0 * N + col] =
                    __floats2half2_rn(geluf(v00 + bv.x), geluf(v01 + bv.y));
                *(__half2*)&outh[(size_t)row1 * N + col] =
                    __floats2half2_rn(geluf(v10 + bv.x), geluf(v11 + bv.y));
            }
        }
    }
}

// ---------------- fp16 tensor-core flash attention ----------------
// 128 threads / 4 warps, 64 q-rows per block (warp -> 16 rows), 64-row K/V tiles.
// All operands half via ldmatrix; softmax in f32.
#define ATS 72  // half stride (144B rows: ldmatrix-conflict-free)
#define ATT_SMEM_BYTES ((64 * ATS /*Q*/ + 2 * 64 * ATS /*K*/ + 2 * 64 * ATS /*V*/ + 64 * ATS /*P*/) * 2)

__global__ void __launch_bounds__(128) attn_h(const __half* __restrict__ Qg,
                                              const __half* __restrict__ Kg,
                                              const __half* __restrict__ Vg,
                                              __half* __restrict__ Og) {
    extern __shared__ __half smh[];
    __half* Qs = smh;                    // [64][ATS]
    __half* Ks = Qs + 64 * ATS;          // [2][64][ATS]
    __half* Vs = Ks + 2 * 64 * ATS;      // [2][64][ATS]
    __half* Ps = Vs + 2 * 64 * ATS;      // [64][ATS]

    int tid = threadIdx.x, lane = tid & 31, warp = tid >> 5;
    int r = lane >> 2, cq = lane & 3;
    int lrow = lane & 15, lhi = (lane >> 4) & 1;
    int q0 = blockIdx.x * 64, bh = blockIdx.y;
    const __half* qp = Qg + (size_t)bh * S_SEQ * HD;
    const __half* kp = Kg + (size_t)bh * S_SEQ * HD;
    const __half* vp = Vg + (size_t)bh * S_SEQ * HD;

    // prologue: stage Q + K0/V0 in one cp.async group
    // 64 rows x 64 halfs = 512 16B-chunks per tile; 128 threads x 4
#pragma unroll
    for (int j = 0; j < 4; j++) {
        int f = tid + 128 * j;
        int row = f >> 3, c8 = (f & 7) * 8;
        cpasync16(&Qs[row * ATS + c8], &qp[(size_t)(q0 + row) * HD + c8]);
        cpasync16(&Ks[row * ATS + c8], &kp[(size_t)row * HD + c8]);
        cpasync16(&Vs[row * ATS + c8], &vp[(size_t)row * HD + c8]);
    }
    cpcommit();

    unsigned qbase = (unsigned)__cvta_generic_to_shared(Qs);
    unsigned pbase = (unsigned)__cvta_generic_to_shared(Ps);
    int qrow = warp * 16 + r;      // C-frag row for this thread
    int qtile = warp * 16;         // warp's 16-row group

    unsigned qa[4][4];
    float m0 = -1e30f, m1 = -1e30f, l0 = 0.f, l1 = 0.f;
    float oacc[8][4];
#pragma unroll
    for (int ni = 0; ni < 8; ni++)
#pragma unroll
        for (int q = 0; q < 4; q++) oacc[ni][q] = 0.f;

    const float scale = 0.125f;  // 64^-0.5
    const int NT = S_SEQ / 64;
    for (int kt = 0; kt < NT; kt++) {
        int buf = kt & 1;
        if (kt + 1 < NT) {
            int nb = 1 - buf;
            const __half* kg = kp + (size_t)(kt + 1) * 64 * HD;
            const __half* vg = vp + (size_t)(kt + 1) * 64 * HD;
            __half* kd = Ks + nb * 64 * ATS;
            __half* vd = Vs + nb * 64 * ATS;
#pragma unroll
            for (int j = 0; j < 4; j++) {
                int f = tid + 128 * j;
                int row = f >> 3, c8 = (f & 7) * 8;
                cpasync16(&kd[row * ATS + c8], &kg[(size_t)row * HD + c8]);
                cpasync16(&vd[row * ATS + c8], &vg[(size_t)row * HD + c8]);
            }
            cpcommit();
            cpwait1();
        } else {
            cpwait0();
        }
        __syncthreads();
        if (kt == 0) {
            // Q frags (A operand): 16 rows x 64 k -> 4 k-steps
#pragma unroll
            for (int kf = 0; kf < 4; kf++) {
                unsigned ad = qbase + ((qtile + lrow) * ATS + kf * 16 + lhi * 8) * 2;
                ldsm4(qa[kf], ad);
            }
        }
        unsigned kbase = (unsigned)__cvta_generic_to_shared(Ks + buf * 64 * ATS);
        unsigned vbase = (unsigned)__cvta_generic_to_shared(Vs + buf * 64 * ATS);

        // ---- S = Q @ K^T (K rows are the n-dim; non-trans ldsm gives B frags) ----
        float s[8][4];
#pragma unroll
        for (int ni = 0; ni < 8; ni++)
#pragma unroll
            for (int q = 0; q < 4; q++) s[ni][q] = 0.f;
#pragma unroll
        for (int kf = 0; kf < 4; kf++) {
#pragma unroll
            for (int ng = 0; ng < 4; ng++) {
                unsigned tmp[4];
                unsigned kd = kbase + ((ng * 16 + lrow) * ATS + kf * 16 + lhi * 8) * 2;
                ldsm4(tmp, kd);
                unsigned b0[2] = {tmp[0], tmp[2]};   // n = ng*16 .. +7
                unsigned b1[2] = {tmp[1], tmp[3]};   // n = ng*16+8 .. +15
                mma16h(s[ng * 2], qa[kf], b0);
                mma16h(s[ng * 2 + 1], qa[kf], b1);
            }
        }

        // ---- online softmax (f32; rows qrow and qrow+8) ----
        float rm0 = -1e30f, rm1 = -1e30f;
#pragma unroll
        for (int ni = 0; ni < 8; ni++) {
            s[ni][0] *= scale; s[ni][1] *= scale;
            s[ni][2] *= scale; s[ni][3] *= scale;
            rm0 = fmaxf(rm0, fmaxf(s[ni][0], s[ni][1]));
            rm1 = fmaxf(rm1, fmaxf(s[ni][2], s[ni][3]));
        }
        rm0 = fmaxf(rm0, __shfl_xor_sync(0xffffffffu, rm0, 1));
        rm0 = fmaxf(rm0, __shfl_xor_sync(0xffffffffu, rm0, 2));
        rm1 = fmaxf(rm1, __shfl_xor_sync(0xffffffffu, rm1, 1));
        rm1 = fmaxf(rm1, __shfl_xor_sync(0xffffffffu, rm1, 2));
        float mn0 = fmaxf(m0, rm0), mn1 = fmaxf(m1, rm1);
        float corr0 = __expf(m0 - mn0), corr1 = __expf(m1 - mn1);
        m0 = mn0; m1 = mn1;
        float rs0 = 0.f, rs1 = 0.f;
#pragma unroll
        for (int ni = 0; ni < 8; ni++) {
            float p0 = __expf(s[ni][0] - mn0);
            float p1 = __expf(s[ni][1] - mn0);
            float p2 = __expf(s[ni][2] - mn1);
            float p3 = __expf(s[ni][3] - mn1);
            rs0 += p0 + p1; rs1 += p2 + p3;
            *(__half2*)&Ps[qrow * ATS + ni * 8 + 2 * cq] = __floats2half2_rn(p0, p1);
            *(__half2*)&Ps[(qrow + 8) * ATS + ni * 8 + 2 * cq] = __floats2half2_rn(p2, p3);
        }
        rs0 += __shfl_xor_sync(0xffffffffu, rs0, 1);
        rs0 += __shfl_xor_sync(0xffffffffu, rs0, 2);
        rs1 += __shfl_xor_sync(0xffffffffu, rs1, 1);
        rs1 += __shfl_xor_sync(0xffffffffu, rs1, 2);
        l0 = l0 * corr0 + rs0;
        l1 = l1 * corr1 + rs1;
#pragma unroll
        for (int ni = 0; ni < 8; ni++) {
            oacc[ni][0] *= corr0; oacc[ni][1] *= corr0;
            oacc[ni][2] *= corr1; oacc[ni][3] *= corr1;
        }
        __syncwarp();  // P rows [warp*16, +16) are warp-private

        // ---- O += P @ V (V rows = k-dim: trans ldsm gives B frags) ----
#pragma unroll
        for (int kc = 0; kc < 4; kc++) {
            unsigned pa[4];
            unsigned pd = pbase + ((qtile + lrow) * ATS + kc * 16 + lhi * 8) * 2;
            ldsm4(pa, pd);
#pragma unroll
            for (int ng = 0; ng < 4; ng++) {
                unsigned tmp[4];
                unsigned vd = vbase + ((kc * 16 + lrow) * ATS + ng * 16 + lhi * 8) * 2;
                ldsm4t(tmp, vd);
                unsigned b0[2] = {tmp[0], tmp[1]};   // n = ng*16 .. +7
                unsigned b1[2] = {tmp[2], tmp[3]};   // n = ng*16+8 .. +15
                mma16h(oacc[ng * 2], pa, b0);
                mma16h(oacc[ng * 2 + 1], pa, b1);
            }
        }
        __syncthreads();
    }

    // normalize + write concat-head layout as half (feeds proj GEMM A)
    int b_ = bh >> 4, h = bh & 15;
    float inv0 = 1.0f / l0, inv1 = 1.0f / l1;
    size_t t0 = ((size_t)b_ * S_SEQ + q0 + qrow) * D_EMB + h * HD;
    size_t t1 = ((size_t)b_ * S_SEQ + q0 + qrow + 8) * D_EMB + h * HD;
#pragma unroll
    for (int ni = 0; ni < 8; ni++) {
        int d = ni * 8 + 2 * cq;
        *(__half2*)&Og[t0 + d] = __floats2half2_rn(oacc[ni][0] * inv0, oacc[ni][1] * inv0);
        *(__half2*)&Og[t1 + d] = __floats2half2_rn(oacc[ni][2] * inv1, oacc[ni][3] * inv1);
    }
}

// ---------------- launch ----------------
extern "C" void kernel_launch(void* const* d_in, const int* in_sizes, int n_in,
                              void* d_out, int out_size) {
    const float* x = (const float*)d_in[0];
    const float* w_qkv = (const float*)d_in[1];
    const float* w_hproj = (const float*)d_in[2];
    const float* b_hproj = (const float*)d_in[3];
    const float* w_out = (const float*)d_in[4];
    const float* b_out = (const float*)d_in[5];
    const float* w_fc1 = (const float*)d_in[6];
    const float* b_fc1 = (const float*)d_in[7];
    const float* w_fc2 = (const float*)d_in[8];
    const float* b_fc2 = (const float*)d_in[9];
    const float* g1 = (const float*)d_in[10];
    const float* be1 = (const float*)d_in[11];
    const float* g2 = (const float*)d_in[12];
    const float* be2 = (const float*)d_in[13];
    float* out = (float*)d_out;

    __half *xnh, *qh, *kh, *vh, *oh, *hh, *W2h, *wqkvph, *wf1h, *wf2h;
    float *x1, *b2;
    cudaGetSymbolAddress((void**)&xnh, g_xnh);
    cudaGetSymbolAddress((void**)&qh, g_qh);
    cudaGetSymbolAddress((void**)&kh, g_kh);
    cudaGetSymbolAddress((void**)&vh, g_vh);
    cudaGetSymbolAddress((void**)&oh, g_oh);
    cudaGetSymbolAddress((void**)&x1, g_x1);
    cudaGetSymbolAddress((void**)&hh, g_hh);
    cudaGetSymbolAddress((void**)&W2h, g_W2h);
    cudaGetSymbolAddress((void**)&b2, g_b2);
    cudaGetSymbolAddress((void**)&wqkvph, g_wqkvph);
    cudaGetSymbolAddress((void**)&wf1h, g_wf1h);
    cudaGetSymbolAddress((void**)&wf2h, g_wf2h);

    cudaFuncSetAttribute(attn_h, cudaFuncAttributeMaxDynamicSharedMemorySize,
                         ATT_SMEM_BYTES);
    cudaFuncSetAttribute(gemm_h<0>, cudaFuncAttributeMaxDynamicSharedMemorySize, GEMM_SMEM);
    cudaFuncSetAttribute(gemm_h<1>, cudaFuncAttributeMaxDynamicSharedMemorySize, GEMM_SMEM);
    cudaFuncSetAttribute(gemm_h<2>, cudaFuncAttributeMaxDynamicSharedMemorySize, GEMM_SMEM);

    // LN1 + weight prep (independent)
    ln_kernel<<<T_TOK, 256>>>(x, g1, be1, xnh);
    repack_qkv_kernel<<<3072, 256>>>(w_qkv, wqkvph);
    fuse_w2_kernel<<<dim3(16, 16), 256>>>(w_hproj, w_out, W2h);
    bias2_kernel<<<64, 256>>>(b_hproj, b_out, w_out, b2);
    f2h_kernel<<<4096, 256>>>(w_fc1, wf1h);
    f2h_kernel<<<4096, 256>>>(w_fc2, wf2h);
    // QKV: [4096,1024] x [1024,3072] -> per-head half q/k/v
    gemm_h<0><<<dim3(32, 24), 256, GEMM_SMEM>>>(xnh, wqkvph, T_TOK, 3072, D_EMB,
                                                nullptr, nullptr, nullptr, nullptr,
                                                qh, kh, vh);
    // fp16 flash attention -> concat-head half
    attn_h<<<dim3(S_SEQ / 64, 32), 128, ATT_SMEM_BYTES>>>(qh, kh, vh, oh);
    // out projection + bias2 + residual -> x1 (f32)
    gemm_h<1><<<dim3(32, 8), 256, GEMM_SMEM>>>(oh, W2h, T_TOK, D_EMB, D_EMB,
                                               b2, x, x1, nullptr,
                                               nullptr, nullptr, nullptr);
    // LN2
    ln_kernel<<<T_TOK, 256>>>(x1, g2, be2, xnh);
    // FC1 + bias + exact GELU -> half
    gemm_h<2><<<dim3(32, 32), 256, GEMM_SMEM>>>(xnh, wf1h, T_TOK, MLP_DIM, D_EMB,
                                                b_fc1, nullptr, nullptr, hh,
                                                nullptr, nullptr, nullptr);
    // FC2 + bias + residual x1 -> out (f32)
    gemm_h<1><<<dim3(32, 8), 256, GEMM_SMEM>>>(hh, wf2h, T_TOK, D_EMB, MLP_DIM,
                                               b_fc2, x1, out, nullptr,
                                               nullptr, nullptr, nullptr);
}